// round 9
// baseline (speedup 1.0000x reference)
#include <cuda_runtime.h>
#include <math.h>

typedef unsigned long long u64;
#define HSZ 512
#define NM  64

__device__ float  d_cF[NM*HSZ], d_sF[NM*HSZ], d_cI[NM*HSZ], d_sI[NM*HSZ];
__device__ float2 d_csI[NM*HSZ];               // interleaved (cI, sI) for K5
__device__ float2 d_t1[64*NM*HSZ];             // interleaved (tr, ti)
__device__ float2 d_xsp[2][64*NM*NM];          // K2 partial sums (w-halves), (xsr,xsi)
__device__ float  d_yfr[64*NM*NM], d_yfi[64*NM*NM];
__device__ float2 d_g[64*HSZ*NM];

__device__ __forceinline__ u64 pk(float lo, float hi){
    u64 r; asm("mov.b64 %0,{%1,%2};" : "=l"(r) : "f"(lo), "f"(hi)); return r; }
__device__ __forceinline__ u64 fma2(u64 a, u64 b, u64 c){
    u64 d; asm("fma.rn.f32x2 %0,%1,%2,%3;" : "=l"(d) : "l"(a), "l"(b), "l"(c)); return d; }
__device__ __forceinline__ float2 upk(u64 a){
    float2 f; asm("mov.b64 {%0,%1},%2;" : "=f"(f.x), "=f"(f.y) : "l"(a)); return f; }
__device__ __forceinline__ float gelu_t(float v){
    float u = 0.7978845608028654f * (v + 0.044715f * v * v * v), t;
    asm("tanh.approx.f32 %0,%1;" : "=f"(t) : "f"(u));
    return 0.5f * v * (1.0f + t); }

__global__ void k_tables(){
    int idx = blockIdx.x * 256 + threadIdx.x;
    int k = idx >> 9, n = idx & 511, t = (k * n) & 511;
    float s, c; sincosf((float)t * 0.012271846303085129f, &s, &c);
    d_cF[idx] = c; d_sF[idx] = s;
    float a = (k == 0 ? 1.0f : 2.0f) * (1.0f / 262144.0f);
    d_cI[idx] = a * c; d_sI[idx] = a * s;
    d_csI[idx] = make_float2(a * c, a * s);
}

// ============ K1: t1[c,kx,w] = sum_h x e^{-i th}  (conflict-free LDS) ============
__global__ void __launch_bounds__(256, 2) k1_fwd_h(const float* __restrict__ x){
    __shared__ float sA[16][128], sB[16][128];
    __shared__ u64 sCt[16][64], sSn[16][64];
    int tid = threadIdx.x, c = blockIdx.y, w0 = blockIdx.x * 128;
    int tw2 = (tid & 15) * 2, tk4 = (tid >> 4) * 4;
    const float* xc = x + (size_t)c * 262144;

    float x0v[8], x2v[8];
#pragma unroll
    for (int p = 0; p < 4; p++){
        float2 v0 = *(const float2*)&xc[w0 + tw2 + 32*p];
        float2 v2 = *(const float2*)&xc[(size_t)256*512 + w0 + tw2 + 32*p];
        x0v[2*p] = v0.x; x0v[2*p+1] = v0.y;
        x2v[2*p] = v2.x; x2v[2*p+1] = v2.y;
    }

    u64 aR[4][4] = {}, aI[4][4] = {};
    for (int h0 = 0; h0 < 256; h0 += 16){
        __syncthreads();
        { int r = tid >> 4, wq = (tid & 15) * 8;
          int hf = h0 + r, hb = (512 - hf) & 511;
          const float* fw = &xc[(size_t)hf*512 + w0 + wq];
          const float* bw = &xc[(size_t)hb*512 + w0 + wq];
#pragma unroll
          for (int q = 0; q < 2; q++){
              float4 f = *(const float4*)&fw[4*q];
              float4 g = *(const float4*)&bw[4*q];
              *(float4*)&sA[r][wq+4*q] = make_float4(f.x+g.x, f.y+g.y, f.z+g.z, f.w+g.w);
              *(float4*)&sB[r][wq+4*q] = make_float4(f.x-g.x, f.y-g.y, f.z-g.z, f.w-g.w);
          } }
        { int kx = tid >> 2, hq = (tid & 3) * 4;
          float4 vc = *(const float4*)&d_cF[kx*512 + h0 + hq];
          float4 vs = *(const float4*)&d_sF[kx*512 + h0 + hq];
          sCt[hq+0][kx]=pk(vc.x,vc.x); sCt[hq+1][kx]=pk(vc.y,vc.y);
          sCt[hq+2][kx]=pk(vc.z,vc.z); sCt[hq+3][kx]=pk(vc.w,vc.w);
          sSn[hq+0][kx]=pk(-vs.x,-vs.x); sSn[hq+1][kx]=pk(-vs.y,-vs.y);
          sSn[hq+2][kx]=pk(-vs.z,-vs.z); sSn[hq+3][kx]=pk(-vs.w,-vs.w); }
        __syncthreads();
#pragma unroll 4
        for (int hh = 0; hh < 16; hh++){
            u64 A[4], B[4];
#pragma unroll
            for (int p = 0; p < 4; p++){
                A[p] = *(const u64*)&sA[hh][tw2 + 32*p];
                B[p] = *(const u64*)&sB[hh][tw2 + 32*p];
            }
#pragma unroll
            for (int j = 0; j < 4; j++){
                u64 C = sCt[hh][tk4+j], S = sSn[hh][tk4+j];
#pragma unroll
                for (int p = 0; p < 4; p++){
                    aR[j][p] = fma2(C, A[p], aR[j][p]);
                    aI[j][p] = fma2(S, B[p], aI[j][p]);
                }
            }
        }
    }
#pragma unroll
    for (int j = 0; j < 4; j++){
        int kx = tk4 + j;
        float sg = (kx & 1) ? -1.0f : 1.0f;
        size_t b = ((size_t)(c*64 + kx))*512 + w0 + tw2;   // float2 elements
#pragma unroll
        for (int p = 0; p < 4; p++){
            float2 tr = upk(aR[j][p]), ti = upk(aI[j][p]);
            tr.x += sg * x2v[2*p]   - x0v[2*p];
            tr.y += sg * x2v[2*p+1] - x0v[2*p+1];
            *(float4*)&d_t1[b + 32*p] = make_float4(tr.x, ti.x, tr.y, ti.y);
        }
    }
}

// ============ K2 v3: packed complex, w-split partials ============
// acc1 = sum (tr,ti)(c,c), acc2 = sum (tr,ti)(s,s)
// xsr = acc1.x + acc2.y ; xsi = acc1.y - acc2.x
__global__ void __launch_bounds__(256) k2_fwd_w(){
    __shared__ float2 sT[32][33];      // [w][ck]
    __shared__ u64 sC[32][65], sS[32][65];  // [w][ky] dup pairs
    int tid = threadIdx.x, ck0 = blockIdx.x * 32, wbase = blockIdx.y * 256;
    int tky4 = (tid & 15) * 4, tck2 = (tid >> 4) * 2;
    u64 a1[2][4] = {}, a2[2][4] = {};
    for (int it = 0; it < 8; it++){
        int w0 = wbase + it * 32;
        __syncthreads();
        { int ckl = tid >> 3, wq = (tid & 7) * 4;
          const float4* tp = (const float4*)&d_t1[(size_t)(ck0+ckl)*512 + w0 + wq];
          float4 v0 = tp[0], v1 = tp[1];
          sT[wq+0][ckl] = make_float2(v0.x, v0.y);
          sT[wq+1][ckl] = make_float2(v0.z, v0.w);
          sT[wq+2][ckl] = make_float2(v1.x, v1.y);
          sT[wq+3][ckl] = make_float2(v1.z, v1.w); }
        { int ky = tid >> 2, w8 = (tid & 3) * 8;
          const float4* cp = (const float4*)&d_cF[ky*512 + w0 + w8];
          const float4* sp = (const float4*)&d_sF[ky*512 + w0 + w8];
          float4 c0 = cp[0], c1 = cp[1], s0 = sp[0], s1 = sp[1];
          sC[w8+0][ky]=pk(c0.x,c0.x); sC[w8+1][ky]=pk(c0.y,c0.y);
          sC[w8+2][ky]=pk(c0.z,c0.z); sC[w8+3][ky]=pk(c0.w,c0.w);
          sC[w8+4][ky]=pk(c1.x,c1.x); sC[w8+5][ky]=pk(c1.y,c1.y);
          sC[w8+6][ky]=pk(c1.z,c1.z); sC[w8+7][ky]=pk(c1.w,c1.w);
          sS[w8+0][ky]=pk(s0.x,s0.x); sS[w8+1][ky]=pk(s0.y,s0.y);
          sS[w8+2][ky]=pk(s0.z,s0.z); sS[w8+3][ky]=pk(s0.w,s0.w);
          sS[w8+4][ky]=pk(s1.x,s1.x); sS[w8+5][ky]=pk(s1.y,s1.y);
          sS[w8+6][ky]=pk(s1.z,s1.z); sS[w8+7][ky]=pk(s1.w,s1.w); }
        __syncthreads();
#pragma unroll 4
        for (int ww = 0; ww < 32; ww++){
            u64 T0 = *(const u64*)&sT[ww][tck2];
            u64 T1 = *(const u64*)&sT[ww][tck2+1];
#pragma unroll
            for (int q = 0; q < 4; q++){
                u64 C = sC[ww][tky4+q], S = sS[ww][tky4+q];
                a1[0][q] = fma2(T0, C, a1[0][q]);  a2[0][q] = fma2(T0, S, a2[0][q]);
                a1[1][q] = fma2(T1, C, a1[1][q]);  a2[1][q] = fma2(T1, S, a2[1][q]);
            }
        }
    }
#pragma unroll
    for (int j = 0; j < 2; j++){
        float2 o_[4];
#pragma unroll
        for (int q = 0; q < 4; q++){
            float2 v1 = upk(a1[j][q]), v2 = upk(a2[j][q]);
            o_[q] = make_float2(v1.x + v2.y, v1.y - v2.x);
        }
        size_t b = (size_t)(ck0 + tck2 + j)*64 + tky4;
        *(float4*)&d_xsp[blockIdx.y][b]     = make_float4(o_[0].x, o_[0].y, o_[1].x, o_[1].y);
        *(float4*)&d_xsp[blockIdx.y][b + 2] = make_float4(o_[2].x, o_[2].y, o_[3].x, o_[3].y);
    }
}

// ============ K3 v2: 512 blocks, sums K2 partials during staging ============
__global__ void __launch_bounds__(256) k3_spectral(const float* __restrict__ wr_,
                                                   const float* __restrict__ wi_){
    __shared__ float2 sX[4096];        // (xsr,xsi) for [i][ky]
    int tid = threadIdx.x, kx = blockIdx.y;
    int o = blockIdx.x * 8 + (tid >> 5), ky2 = (tid & 31) * 2;
#pragma unroll
    for (int p = 0; p < 16; p++){
        int idx = tid + 256*p;         // idx = i*64 + ky
        size_t g = ((size_t)(idx >> 6))*4096 + kx*64 + (idx & 63);
        float2 a = d_xsp[0][g], b = d_xsp[1][g];
        sX[idx] = make_float2(a.x + b.x, a.y + b.y);
    }
    __syncthreads();
    float2 accR = {0,0}, accI = {0,0};
#pragma unroll 8
    for (int i = 0; i < 64; i++){
        size_t wb = ((size_t)((i*64 + o)*64 + kx))*64 + ky2;
        float2 wr = *(const float2*)&wr_[wb], wi = *(const float2*)&wi_[wb];
        float2 x0 = sX[i*64 + ky2], x1 = sX[i*64 + ky2 + 1];
        accR.x += x0.x*wr.x - x0.y*wi.x;  accI.x += x0.x*wi.x + x0.y*wr.x;
        accR.y += x1.x*wr.y - x1.y*wi.y;  accI.y += x1.x*wi.y + x1.y*wr.y;
    }
    size_t ob = (size_t)(o*64 + kx)*64 + ky2;
    *(float2*)&d_yfr[ob] = accR;
    *(float2*)&d_yfi[ob] = accI;
}

// ============ K4 (scalar): g[o,h,ky] = sum_kx yf e^{+i 2pi kx h/512} ============
__global__ void __launch_bounds__(256) k4_inv_h(){
    __shared__ float sYr[32][64], sYi[32][64], sC[32][64], sS[32][64];
    int tid = threadIdx.x, h0 = blockIdx.x * 64, o = blockIdx.y;
    int ky0 = (tid & 15) * 4, hb = (tid >> 4) * 4;
    float gR[4][4] = {}, gI[4][4] = {};
    for (int kx0 = 0; kx0 < 64; kx0 += 32){
        __syncthreads();
        { int k = tid >> 3, q8 = (tid & 7) * 8;
          const float4* yr = (const float4*)&d_yfr[(size_t)(o*64 + kx0 + k)*64 + q8];
          const float4* yi = (const float4*)&d_yfi[(size_t)(o*64 + kx0 + k)*64 + q8];
          *(float4*)&sYr[k][q8] = yr[0]; *(float4*)&sYr[k][q8+4] = yr[1];
          *(float4*)&sYi[k][q8] = yi[0]; *(float4*)&sYi[k][q8+4] = yi[1];
          const float4* cp = (const float4*)&d_cF[(kx0+k)*512 + h0 + q8];
          const float4* sp = (const float4*)&d_sF[(kx0+k)*512 + h0 + q8];
          *(float4*)&sC[k][q8] = cp[0]; *(float4*)&sC[k][q8+4] = cp[1];
          *(float4*)&sS[k][q8] = sp[0]; *(float4*)&sS[k][q8+4] = sp[1]; }
        __syncthreads();
#pragma unroll 4
        for (int k = 0; k < 32; k++){
            float yr[4], yi[4];
#pragma unroll
            for (int q = 0; q < 4; q++){ yr[q] = sYr[k][ky0+q]; yi[q] = sYi[k][ky0+q]; }
#pragma unroll
            for (int jh = 0; jh < 4; jh++){
                float cv = sC[k][hb+jh], sv = sS[k][hb+jh];
#pragma unroll
                for (int q = 0; q < 4; q++){
                    gR[jh][q] += yr[q]*cv - yi[q]*sv;
                    gI[jh][q] += yr[q]*sv + yi[q]*cv;
                }
            }
        }
    }
#pragma unroll
    for (int jh = 0; jh < 4; jh++){
        float2* dst = &d_g[((size_t)o*512 + h0 + hb + jh)*64 + ky0];
#pragma unroll
        for (int q = 0; q < 4; q++) dst[q] = make_float2(gR[jh][q], gI[jh][q]);
    }
}

// ============ K5 v2: (u,v)-packed conv + skip + bias + gelu ============
__global__ void __launch_bounds__(128, 4) k5_inv_w(const float* __restrict__ x,
        const float* __restrict__ b_conv, const float* __restrict__ w_skip,
        const float* __restrict__ b_skip, float* __restrict__ out){
    __shared__ float2 sG[16*64];
    __shared__ u64    sW[16*64];
    __shared__ float  sCv[16*512];

    int tid = threadIdx.x, o0 = blockIdx.x * 16, h = blockIdx.y;
    int og = tid >> 5, wg = tid & 31;

#pragma unroll
    for (int q = 0; q < 8; q++){
        int id = tid + 128*q, oo = id >> 6, k = id & 63;
        sG[id] = d_g[((size_t)(o0+oo)*512 + h)*64 + k];
        float wv = w_skip[(o0+oo)*64 + k];
        sW[id] = pk(wv, wv);
    }
    __syncthreads();

    u64 acc[4][8] = {};
#pragma unroll 2
    for (int ky = 0; ky < 64; ky++){
        u64 T[8];
#pragma unroll
        for (int p = 0; p < 8; p++)
            T[p] = *(const u64*)&d_csI[ky*512 + wg + 32*p];
#pragma unroll
        for (int oo = 0; oo < 4; oo++){
            u64 G = *(const u64*)&sG[(og*4 + oo)*64 + ky];
#pragma unroll
            for (int p = 0; p < 8; p++)
                acc[oo][p] = fma2(G, T[p], acc[oo][p]);
        }
    }
#pragma unroll
    for (int oo = 0; oo < 4; oo++){
        int o = og*4 + oo;
#pragma unroll
        for (int p = 0; p < 8; p++){
            int w = wg + 32*p;
            float2 uv = upk(acc[oo][p]);
            sCv[o*512 + w] = uv.x - uv.y;
            if (w) sCv[o*512 + 512 - w] = uv.x + uv.y;
        }
    }
    if (tid < 16){
        float s = 0.0f;
        for (int k = 0; k < 64; k++){
            float coef = (k == 0 ? 1.0f : 2.0f) * ((k & 1) ? -3.814697265625e-06f
                                                           :  3.814697265625e-06f);
            s += sG[tid*64 + k].x * coef;
        }
        sCv[tid*512 + 256] = s;
    }
    __syncthreads();

    u64 a0[16] = {}, a1[16] = {};
    const float* xh = x + (size_t)h*512 + 2*tid;
#pragma unroll 4
    for (int i = 0; i < 64; i++){
        u64 X0 = *(const u64*)&xh[(size_t)i*262144];
        u64 X1 = *(const u64*)&xh[(size_t)i*262144 + 256];
#pragma unroll
        for (int oo = 0; oo < 16; oo++){
            u64 W = sW[oo*64 + i];
            a0[oo] = fma2(W, X0, a0[oo]);
            a1[oo] = fma2(W, X1, a1[oo]);
        }
    }

#pragma unroll
    for (int oo = 0; oo < 16; oo++){
        int o = o0 + oo;
        float bias = b_conv[o] + b_skip[o];
        float2 c0 = *(const float2*)&sCv[oo*512 + 2*tid];
        float2 c1 = *(const float2*)&sCv[oo*512 + 256 + 2*tid];
        float2 s0 = upk(a0[oo]), s1 = upk(a1[oo]);
        float2 r0 = make_float2(gelu_t(s0.x + c0.x + bias), gelu_t(s0.y + c0.y + bias));
        float2 r1 = make_float2(gelu_t(s1.x + c1.x + bias), gelu_t(s1.y + c1.y + bias));
        size_t obase = (size_t)o*262144 + (size_t)h*512 + 2*tid;
        *(float2*)&out[obase]       = r0;
        *(float2*)&out[obase + 256] = r1;
    }
}

extern "C" void kernel_launch(void* const* d_in, const int* in_sizes, int n_in,
                              void* d_out, int out_size){
    const float* x      = (const float*)d_in[0];
    const float* w_real = (const float*)d_in[1];
    const float* w_imag = (const float*)d_in[2];
    const float* b_conv = (const float*)d_in[3];
    const float* w_skip = (const float*)d_in[4];
    const float* b_skip = (const float*)d_in[5];
    float* out = (float*)d_out;

    // capture slot (launch index 3) = k2_fwd_w
    k_tables<<<128, 256>>>();
    k_tables<<<128, 256>>>();
    k1_fwd_h<<<dim3(4, 64), 256>>>(x);
    k2_fwd_w<<<dim3(128, 2), 256>>>();
    k3_spectral<<<dim3(8, 64), 256>>>(w_real, w_imag);
    k4_inv_h<<<dim3(8, 64), 256>>>();
    k5_inv_w<<<dim3(4, 512), 128>>>(x, b_conv, w_skip, b_skip, out);
}

// round 10
// speedup vs baseline: 1.1443x; 1.1443x over previous
#include <cuda_runtime.h>
#include <math.h>

typedef unsigned long long u64;
#define HSZ 512
#define NM  64

__device__ float  d_cF[NM*HSZ], d_sF[NM*HSZ], d_cI[NM*HSZ], d_sI[NM*HSZ];
__device__ float2 d_csI[NM*HSZ];               // interleaved (cI, sI) for K5
__device__ float2 d_t1[64*NM*HSZ];             // interleaved (tr, ti)
__device__ float2 d_xsp[2][64*NM*NM];          // K2 partial sums (w-halves), (xsr,xsi)
__device__ float  d_yfr[64*NM*NM], d_yfi[64*NM*NM];
__device__ float2 d_g[64*HSZ*NM];

__device__ __forceinline__ u64 pk(float lo, float hi){
    u64 r; asm("mov.b64 %0,{%1,%2};" : "=l"(r) : "f"(lo), "f"(hi)); return r; }
__device__ __forceinline__ u64 fma2(u64 a, u64 b, u64 c){
    u64 d; asm("fma.rn.f32x2 %0,%1,%2,%3;" : "=l"(d) : "l"(a), "l"(b), "l"(c)); return d; }
__device__ __forceinline__ float2 upk(u64 a){
    float2 f; asm("mov.b64 {%0,%1},%2;" : "=f"(f.x), "=f"(f.y) : "l"(a)); return f; }
__device__ __forceinline__ float gelu_t(float v){
    float u = 0.7978845608028654f * (v + 0.044715f * v * v * v), t;
    asm("tanh.approx.f32 %0,%1;" : "=f"(t) : "f"(u));
    return 0.5f * v * (1.0f + t); }

__global__ void k_tables(){
    int idx = blockIdx.x * 256 + threadIdx.x;
    int k = idx >> 9, n = idx & 511, t = (k * n) & 511;
    float s, c; sincosf((float)t * 0.012271846303085129f, &s, &c);
    d_cF[idx] = c; d_sF[idx] = s;
    float a = (k == 0 ? 1.0f : 2.0f) * (1.0f / 262144.0f);
    d_cI[idx] = a * c; d_sI[idx] = a * s;
    d_csI[idx] = make_float2(a * c, a * s);
}

// ============ K1: t1[c,kx,w] = sum_h x e^{-i th}  (conflict-free LDS) ============
__global__ void __launch_bounds__(256, 2) k1_fwd_h(const float* __restrict__ x){
    __shared__ float sA[16][128], sB[16][128];
    __shared__ u64 sCt[16][64], sSn[16][64];
    int tid = threadIdx.x, c = blockIdx.y, w0 = blockIdx.x * 128;
    int tw2 = (tid & 15) * 2, tk4 = (tid >> 4) * 4;
    const float* xc = x + (size_t)c * 262144;

    float x0v[8], x2v[8];
#pragma unroll
    for (int p = 0; p < 4; p++){
        float2 v0 = *(const float2*)&xc[w0 + tw2 + 32*p];
        float2 v2 = *(const float2*)&xc[(size_t)256*512 + w0 + tw2 + 32*p];
        x0v[2*p] = v0.x; x0v[2*p+1] = v0.y;
        x2v[2*p] = v2.x; x2v[2*p+1] = v2.y;
    }

    u64 aR[4][4] = {}, aI[4][4] = {};
    for (int h0 = 0; h0 < 256; h0 += 16){
        __syncthreads();
        { int r = tid >> 4, wq = (tid & 15) * 8;
          int hf = h0 + r, hb = (512 - hf) & 511;
          const float* fw = &xc[(size_t)hf*512 + w0 + wq];
          const float* bw = &xc[(size_t)hb*512 + w0 + wq];
#pragma unroll
          for (int q = 0; q < 2; q++){
              float4 f = *(const float4*)&fw[4*q];
              float4 g = *(const float4*)&bw[4*q];
              *(float4*)&sA[r][wq+4*q] = make_float4(f.x+g.x, f.y+g.y, f.z+g.z, f.w+g.w);
              *(float4*)&sB[r][wq+4*q] = make_float4(f.x-g.x, f.y-g.y, f.z-g.z, f.w-g.w);
          } }
        { int kx = tid >> 2, hq = (tid & 3) * 4;
          float4 vc = *(const float4*)&d_cF[kx*512 + h0 + hq];
          float4 vs = *(const float4*)&d_sF[kx*512 + h0 + hq];
          sCt[hq+0][kx]=pk(vc.x,vc.x); sCt[hq+1][kx]=pk(vc.y,vc.y);
          sCt[hq+2][kx]=pk(vc.z,vc.z); sCt[hq+3][kx]=pk(vc.w,vc.w);
          sSn[hq+0][kx]=pk(-vs.x,-vs.x); sSn[hq+1][kx]=pk(-vs.y,-vs.y);
          sSn[hq+2][kx]=pk(-vs.z,-vs.z); sSn[hq+3][kx]=pk(-vs.w,-vs.w); }
        __syncthreads();
#pragma unroll 4
        for (int hh = 0; hh < 16; hh++){
            u64 A[4], B[4];
#pragma unroll
            for (int p = 0; p < 4; p++){
                A[p] = *(const u64*)&sA[hh][tw2 + 32*p];
                B[p] = *(const u64*)&sB[hh][tw2 + 32*p];
            }
#pragma unroll
            for (int j = 0; j < 4; j++){
                u64 C = sCt[hh][tk4+j], S = sSn[hh][tk4+j];
#pragma unroll
                for (int p = 0; p < 4; p++){
                    aR[j][p] = fma2(C, A[p], aR[j][p]);
                    aI[j][p] = fma2(S, B[p], aI[j][p]);
                }
            }
        }
    }
#pragma unroll
    for (int j = 0; j < 4; j++){
        int kx = tk4 + j;
        float sg = (kx & 1) ? -1.0f : 1.0f;
        size_t b = ((size_t)(c*64 + kx))*512 + w0 + tw2;   // float2 elements
#pragma unroll
        for (int p = 0; p < 4; p++){
            float2 tr = upk(aR[j][p]), ti = upk(aI[j][p]);
            tr.x += sg * x2v[2*p]   - x0v[2*p];
            tr.y += sg * x2v[2*p+1] - x0v[2*p+1];
            *(float4*)&d_t1[b + 32*p] = make_float4(tr.x, ti.x, tr.y, ti.y);
        }
    }
}

// ============ K2 v4: packed complex, conflict-free interleaved ky mapping ============
// acc1 = sum (tr,ti)(c,c), acc2 = sum (tr,ti)(s,s)
// xsr = acc1.x + acc2.y ; xsi = acc1.y - acc2.x
// thread ky set: (tid&15) + 16q  -> lanes 0-15 read consecutive u64 (no conflicts)
__global__ void __launch_bounds__(256) k2_fwd_w(){
    __shared__ float2 sT[32][33];            // [w][ck]
    __shared__ u64 sC[32][65], sS[32][65];   // [w][ky] dup pairs
    int tid = threadIdx.x, ck0 = blockIdx.x * 32, wbase = blockIdx.y * 256;
    int kyl = tid & 15, tck2 = (tid >> 4) * 2;
    u64 a1[2][4] = {}, a2[2][4] = {};
    for (int it = 0; it < 8; it++){
        int w0 = wbase + it * 32;
        __syncthreads();
        { int ckl = tid >> 3, wq = (tid & 7) * 4;
          const float4* tp = (const float4*)&d_t1[(size_t)(ck0+ckl)*512 + w0 + wq];
          float4 v0 = tp[0], v1 = tp[1];
          sT[wq+0][ckl] = make_float2(v0.x, v0.y);
          sT[wq+1][ckl] = make_float2(v0.z, v0.w);
          sT[wq+2][ckl] = make_float2(v1.x, v1.y);
          sT[wq+3][ckl] = make_float2(v1.z, v1.w); }
        { int ky = tid >> 2, w8 = (tid & 3) * 8;
          const float4* cp = (const float4*)&d_cF[ky*512 + w0 + w8];
          const float4* sp = (const float4*)&d_sF[ky*512 + w0 + w8];
          float4 c0 = cp[0], c1 = cp[1], s0 = sp[0], s1 = sp[1];
          sC[w8+0][ky]=pk(c0.x,c0.x); sC[w8+1][ky]=pk(c0.y,c0.y);
          sC[w8+2][ky]=pk(c0.z,c0.z); sC[w8+3][ky]=pk(c0.w,c0.w);
          sC[w8+4][ky]=pk(c1.x,c1.x); sC[w8+5][ky]=pk(c1.y,c1.y);
          sC[w8+6][ky]=pk(c1.z,c1.z); sC[w8+7][ky]=pk(c1.w,c1.w);
          sS[w8+0][ky]=pk(s0.x,s0.x); sS[w8+1][ky]=pk(s0.y,s0.y);
          sS[w8+2][ky]=pk(s0.z,s0.z); sS[w8+3][ky]=pk(s0.w,s0.w);
          sS[w8+4][ky]=pk(s1.x,s1.x); sS[w8+5][ky]=pk(s1.y,s1.y);
          sS[w8+6][ky]=pk(s1.z,s1.z); sS[w8+7][ky]=pk(s1.w,s1.w); }
        __syncthreads();
#pragma unroll 4
        for (int ww = 0; ww < 32; ww++){
            u64 T0 = *(const u64*)&sT[ww][tck2];
            u64 T1 = *(const u64*)&sT[ww][tck2+1];
#pragma unroll
            for (int q = 0; q < 4; q++){
                u64 C = sC[ww][kyl + 16*q], S = sS[ww][kyl + 16*q];
                a1[0][q] = fma2(T0, C, a1[0][q]);  a2[0][q] = fma2(T0, S, a2[0][q]);
                a1[1][q] = fma2(T1, C, a1[1][q]);  a2[1][q] = fma2(T1, S, a2[1][q]);
            }
        }
    }
#pragma unroll
    for (int j = 0; j < 2; j++){
        size_t row = (size_t)(ck0 + tck2 + j)*64;
#pragma unroll
        for (int q = 0; q < 4; q++){
            float2 v1 = upk(a1[j][q]), v2 = upk(a2[j][q]);
            d_xsp[blockIdx.y][row + kyl + 16*q] = make_float2(v1.x + v2.y, v1.y - v2.x);
        }
    }
}

// ============ K3 v2: 512 blocks, sums K2 partials during staging ============
__global__ void __launch_bounds__(256) k3_spectral(const float* __restrict__ wr_,
                                                   const float* __restrict__ wi_){
    __shared__ float2 sX[4096];        // (xsr,xsi) for [i][ky]
    int tid = threadIdx.x, kx = blockIdx.y;
    int o = blockIdx.x * 8 + (tid >> 5), ky2 = (tid & 31) * 2;
#pragma unroll
    for (int p = 0; p < 16; p++){
        int idx = tid + 256*p;         // idx = i*64 + ky
        size_t g = ((size_t)(idx >> 6))*4096 + kx*64 + (idx & 63);
        float2 a = d_xsp[0][g], b = d_xsp[1][g];
        sX[idx] = make_float2(a.x + b.x, a.y + b.y);
    }
    __syncthreads();
    float2 accR = {0,0}, accI = {0,0};
#pragma unroll 8
    for (int i = 0; i < 64; i++){
        size_t wb = ((size_t)((i*64 + o)*64 + kx))*64 + ky2;
        float2 wr = *(const float2*)&wr_[wb], wi = *(const float2*)&wi_[wb];
        float2 x0 = sX[i*64 + ky2], x1 = sX[i*64 + ky2 + 1];
        accR.x += x0.x*wr.x - x0.y*wi.x;  accI.x += x0.x*wi.x + x0.y*wr.x;
        accR.y += x1.x*wr.y - x1.y*wi.y;  accI.y += x1.x*wi.y + x1.y*wr.y;
    }
    size_t ob = (size_t)(o*64 + kx)*64 + ky2;
    *(float2*)&d_yfr[ob] = accR;
    *(float2*)&d_yfi[ob] = accI;
}

// ============ K4 (scalar): g[o,h,ky] = sum_kx yf e^{+i 2pi kx h/512} ============
__global__ void __launch_bounds__(256) k4_inv_h(){
    __shared__ float sYr[32][64], sYi[32][64], sC[32][64], sS[32][64];
    int tid = threadIdx.x, h0 = blockIdx.x * 64, o = blockIdx.y;
    int ky0 = (tid & 15) * 4, hb = (tid >> 4) * 4;
    float gR[4][4] = {}, gI[4][4] = {};
    for (int kx0 = 0; kx0 < 64; kx0 += 32){
        __syncthreads();
        { int k = tid >> 3, q8 = (tid & 7) * 8;
          const float4* yr = (const float4*)&d_yfr[(size_t)(o*64 + kx0 + k)*64 + q8];
          const float4* yi = (const float4*)&d_yfi[(size_t)(o*64 + kx0 + k)*64 + q8];
          *(float4*)&sYr[k][q8] = yr[0]; *(float4*)&sYr[k][q8+4] = yr[1];
          *(float4*)&sYi[k][q8] = yi[0]; *(float4*)&sYi[k][q8+4] = yi[1];
          const float4* cp = (const float4*)&d_cF[(kx0+k)*512 + h0 + q8];
          const float4* sp = (const float4*)&d_sF[(kx0+k)*512 + h0 + q8];
          *(float4*)&sC[k][q8] = cp[0]; *(float4*)&sC[k][q8+4] = cp[1];
          *(float4*)&sS[k][q8] = sp[0]; *(float4*)&sS[k][q8+4] = sp[1]; }
        __syncthreads();
#pragma unroll 4
        for (int k = 0; k < 32; k++){
            float yr[4], yi[4];
#pragma unroll
            for (int q = 0; q < 4; q++){ yr[q] = sYr[k][ky0+q]; yi[q] = sYi[k][ky0+q]; }
#pragma unroll
            for (int jh = 0; jh < 4; jh++){
                float cv = sC[k][hb+jh], sv = sS[k][hb+jh];
#pragma unroll
                for (int q = 0; q < 4; q++){
                    gR[jh][q] += yr[q]*cv - yi[q]*sv;
                    gI[jh][q] += yr[q]*sv + yi[q]*cv;
                }
            }
        }
    }
#pragma unroll
    for (int jh = 0; jh < 4; jh++){
        float2* dst = &d_g[((size_t)o*512 + h0 + hb + jh)*64 + ky0];
#pragma unroll
        for (int q = 0; q < 4; q++) dst[q] = make_float2(gR[jh][q], gI[jh][q]);
    }
}

// ============ K5 v2: (u,v)-packed conv + skip + bias + gelu ============
__global__ void __launch_bounds__(128, 4) k5_inv_w(const float* __restrict__ x,
        const float* __restrict__ b_conv, const float* __restrict__ w_skip,
        const float* __restrict__ b_skip, float* __restrict__ out){
    __shared__ float2 sG[16*64];
    __shared__ u64    sW[16*64];
    __shared__ float  sCv[16*512];

    int tid = threadIdx.x, o0 = blockIdx.x * 16, h = blockIdx.y;
    int og = tid >> 5, wg = tid & 31;

#pragma unroll
    for (int q = 0; q < 8; q++){
        int id = tid + 128*q, oo = id >> 6, k = id & 63;
        sG[id] = d_g[((size_t)(o0+oo)*512 + h)*64 + k];
        float wv = w_skip[(o0+oo)*64 + k];
        sW[id] = pk(wv, wv);
    }
    __syncthreads();

    u64 acc[4][8] = {};
#pragma unroll 2
    for (int ky = 0; ky < 64; ky++){
        u64 T[8];
#pragma unroll
        for (int p = 0; p < 8; p++)
            T[p] = *(const u64*)&d_csI[ky*512 + wg + 32*p];
#pragma unroll
        for (int oo = 0; oo < 4; oo++){
            u64 G = *(const u64*)&sG[(og*4 + oo)*64 + ky];
#pragma unroll
            for (int p = 0; p < 8; p++)
                acc[oo][p] = fma2(G, T[p], acc[oo][p]);
        }
    }
#pragma unroll
    for (int oo = 0; oo < 4; oo++){
        int o = og*4 + oo;
#pragma unroll
        for (int p = 0; p < 8; p++){
            int w = wg + 32*p;
            float2 uv = upk(acc[oo][p]);
            sCv[o*512 + w] = uv.x - uv.y;
            if (w) sCv[o*512 + 512 - w] = uv.x + uv.y;
        }
    }
    if (tid < 16){
        float s = 0.0f;
        for (int k = 0; k < 64; k++){
            float coef = (k == 0 ? 1.0f : 2.0f) * ((k & 1) ? -3.814697265625e-06f
                                                           :  3.814697265625e-06f);
            s += sG[tid*64 + k].x * coef;
        }
        sCv[tid*512 + 256] = s;
    }
    __syncthreads();

    u64 a0[16] = {}, a1[16] = {};
    const float* xh = x + (size_t)h*512 + 2*tid;
#pragma unroll 4
    for (int i = 0; i < 64; i++){
        u64 X0 = *(const u64*)&xh[(size_t)i*262144];
        u64 X1 = *(const u64*)&xh[(size_t)i*262144 + 256];
#pragma unroll
        for (int oo = 0; oo < 16; oo++){
            u64 W = sW[oo*64 + i];
            a0[oo] = fma2(W, X0, a0[oo]);
            a1[oo] = fma2(W, X1, a1[oo]);
        }
    }

#pragma unroll
    for (int oo = 0; oo < 16; oo++){
        int o = o0 + oo;
        float bias = b_conv[o] + b_skip[o];
        float2 c0 = *(const float2*)&sCv[oo*512 + 2*tid];
        float2 c1 = *(const float2*)&sCv[oo*512 + 256 + 2*tid];
        float2 s0 = upk(a0[oo]), s1 = upk(a1[oo]);
        float2 r0 = make_float2(gelu_t(s0.x + c0.x + bias), gelu_t(s0.y + c0.y + bias));
        float2 r1 = make_float2(gelu_t(s1.x + c1.x + bias), gelu_t(s1.y + c1.y + bias));
        size_t obase = (size_t)o*262144 + (size_t)h*512 + 2*tid;
        *(float2*)&out[obase]       = r0;
        *(float2*)&out[obase + 256] = r1;
    }
}

extern "C" void kernel_launch(void* const* d_in, const int* in_sizes, int n_in,
                              void* d_out, int out_size){
    const float* x      = (const float*)d_in[0];
    const float* w_real = (const float*)d_in[1];
    const float* w_imag = (const float*)d_in[2];
    const float* b_conv = (const float*)d_in[3];
    const float* w_skip = (const float*)d_in[4];
    const float* b_skip = (const float*)d_in[5];
    float* out = (float*)d_out;

    // capture slot (launch index 3) = k2_fwd_w
    k_tables<<<128, 256>>>();
    k_tables<<<128, 256>>>();
    k1_fwd_h<<<dim3(4, 64), 256>>>(x);
    k2_fwd_w<<<dim3(128, 2), 256>>>();
    k3_spectral<<<dim3(8, 64), 256>>>(w_real, w_imag);
    k4_inv_h<<<dim3(8, 64), 256>>>();
    k5_inv_w<<<dim3(4, 512), 128>>>(x, b_conv, w_skip, b_skip, out);
}

// round 11
// speedup vs baseline: 1.2677x; 1.1079x over previous
#include <cuda_runtime.h>
#include <math.h>

typedef unsigned long long u64;
#define HSZ 512
#define NM  64

__device__ float  d_cF[NM*HSZ], d_sF[NM*HSZ], d_cI[NM*HSZ], d_sI[NM*HSZ];
__device__ float2 d_csI[NM*HSZ];               // interleaved (cI, sI) for K5
__device__ float2 d_t1[64*NM*HSZ];             // interleaved (tr, ti)
__device__ float2 d_xsp[2][64*NM*NM];          // K2 partial sums (w-halves)
__device__ float  d_yfr[64*NM*NM], d_yfi[64*NM*NM];
__device__ float2 d_g[64*HSZ*NM];

__device__ __forceinline__ u64 pk(float lo, float hi){
    u64 r; asm("mov.b64 %0,{%1,%2};" : "=l"(r) : "f"(lo), "f"(hi)); return r; }
__device__ __forceinline__ u64 fma2(u64 a, u64 b, u64 c){
    u64 d; asm("fma.rn.f32x2 %0,%1,%2,%3;" : "=l"(d) : "l"(a), "l"(b), "l"(c)); return d; }
__device__ __forceinline__ float2 upk(u64 a){
    float2 f; asm("mov.b64 {%0,%1},%2;" : "=f"(f.x), "=f"(f.y) : "l"(a)); return f; }
__device__ __forceinline__ float gelu_t(float v){
    float u = 0.7978845608028654f * (v + 0.044715f * v * v * v), t;
    asm("tanh.approx.f32 %0,%1;" : "=f"(t) : "f"(u));
    return 0.5f * v * (1.0f + t); }

__global__ void k_tables(){
    int idx = blockIdx.x * 256 + threadIdx.x;
    int k = idx >> 9, n = idx & 511, t = (k * n) & 511;
    float s, c; sincosf((float)t * 0.012271846303085129f, &s, &c);
    d_cF[idx] = c; d_sF[idx] = s;
    float a = (k == 0 ? 1.0f : 2.0f) * (1.0f / 262144.0f);
    d_cI[idx] = a * c; d_sI[idx] = a * s;
    d_csI[idx] = make_float2(a * c, a * s);
}

// ============ K1 v3: quarter-wave double fold, parity-specialized warps ============
// Even k: tr = sum_{h<128} Ae*cos + x256 - x0 + (-1)^(k/2)*A128 ; ti = -sum Be*sin
// Odd  k: tr = sum Ao*cos - x256 - x0 ;  ti = -sum Bo*sin - (-1)^((k-1)/2)*B128
// Ae=(a+b)+(c+d), Ao=(a+b)-(c+d), Be=(a-b)-(c-d), Bo=(a-b)+(c-d)
//   with a=x[h], b=x[512-h], c=x[256-h], d=x[256+h] (c,d masked at h=0)
__global__ void __launch_bounds__(256, 2) k1_fwd_h(const float* __restrict__ x){
    __shared__ float sAe[16][128], sAo[16][128], sBe[16][128], sBo[16][128];
    __shared__ u64 sCt[16][64], sSn[16][64];
    int tid = threadIdx.x, c = blockIdx.y, w0 = blockIdx.x * 128;
    int tw2 = (tid & 15) * 2;
    int g = tid >> 4;                 // 0..15; g<8 even kx, g>=8 odd kx
    int par = g >> 3;                 // 0 even, 1 odd
    int kbase = (g & 7) * 8 + par;    // kx = kbase + 2j
    const float* xc = x + (size_t)c * 262144;

    u64 aR[4][4] = {}, aI[4][4] = {};
    for (int h0 = 0; h0 < 128; h0 += 16){
        __syncthreads();
        {   int r = tid >> 4, wq = (tid & 15) * 8;
            int hf = h0 + r;
            const float* pa = &xc[(size_t)hf*512 + w0 + wq];
            const float* pb = &xc[(size_t)((512 - hf) & 511)*512 + w0 + wq];
            const float* pc = &xc[(size_t)(256 - hf)*512 + w0 + wq];
            const float* pd = &xc[(size_t)(256 + hf)*512 + w0 + wq];
            float pe = (hf == 0) ? 0.0f : 1.0f;
#pragma unroll
            for (int q = 0; q < 2; q++){
                float4 va = *(const float4*)&pa[4*q];
                float4 vb = *(const float4*)&pb[4*q];
                float4 vc = *(const float4*)&pc[4*q];
                float4 vd = *(const float4*)&pd[4*q];
                float4 e4, o4, be4, bo4;
#pragma unroll
                for (int e = 0; e < 4; e++){
                    float fa = (&va.x)[e], fb = (&vb.x)[e];
                    float fc = (&vc.x)[e] * pe, fd = (&vd.x)[e] * pe;
                    float sab = fa + fb, dab = fa - fb;
                    float scd = fc + fd, dcd = fc - fd;
                    (&e4.x)[e]  = sab + scd;
                    (&o4.x)[e]  = sab - scd;
                    (&be4.x)[e] = dab - dcd;
                    (&bo4.x)[e] = dab + dcd;
                }
                *(float4*)&sAe[r][wq+4*q] = e4;
                *(float4*)&sAo[r][wq+4*q] = o4;
                *(float4*)&sBe[r][wq+4*q] = be4;
                *(float4*)&sBo[r][wq+4*q] = bo4;
            }
        }
        {   int kx = tid >> 2, hq = (tid & 3) * 4;
            float4 vc = *(const float4*)&d_cF[kx*512 + h0 + hq];
            float4 vs = *(const float4*)&d_sF[kx*512 + h0 + hq];
            sCt[hq+0][kx]=pk(vc.x,vc.x); sCt[hq+1][kx]=pk(vc.y,vc.y);
            sCt[hq+2][kx]=pk(vc.z,vc.z); sCt[hq+3][kx]=pk(vc.w,vc.w);
            sSn[hq+0][kx]=pk(-vs.x,-vs.x); sSn[hq+1][kx]=pk(-vs.y,-vs.y);
            sSn[hq+2][kx]=pk(-vs.z,-vs.z); sSn[hq+3][kx]=pk(-vs.w,-vs.w);
        }
        __syncthreads();
        const float* rowA = par ? &sAo[0][0] : &sAe[0][0];
        const float* rowB = par ? &sBo[0][0] : &sBe[0][0];
#pragma unroll 4
        for (int hh = 0; hh < 16; hh++){
            u64 A[4], B[4];
#pragma unroll
            for (int p = 0; p < 4; p++){
                A[p] = *(const u64*)&rowA[hh*128 + tw2 + 32*p];
                B[p] = *(const u64*)&rowB[hh*128 + tw2 + 32*p];
            }
#pragma unroll
            for (int j = 0; j < 4; j++){
                u64 C = sCt[hh][kbase + 2*j], S = sSn[hh][kbase + 2*j];
#pragma unroll
                for (int p = 0; p < 4; p++){
                    aR[j][p] = fma2(C, A[p], aR[j][p]);
                    aI[j][p] = fma2(S, B[p], aI[j][p]);
                }
            }
        }
    }

    // epilogue: corrections loaded here (not held live through mainloop)
    float x0v[8], x2v[8], a128[8], b128[8];
#pragma unroll
    for (int p = 0; p < 4; p++){
        float2 v0 = *(const float2*)&xc[w0 + tw2 + 32*p];
        float2 v2 = *(const float2*)&xc[(size_t)256*512 + w0 + tw2 + 32*p];
        float2 va = *(const float2*)&xc[(size_t)128*512 + w0 + tw2 + 32*p];
        float2 vb = *(const float2*)&xc[(size_t)384*512 + w0 + tw2 + 32*p];
        x0v[2*p]=v0.x; x0v[2*p+1]=v0.y;
        x2v[2*p]=v2.x; x2v[2*p+1]=v2.y;
        a128[2*p]=va.x+vb.x; a128[2*p+1]=va.y+vb.y;
        b128[2*p]=va.x-vb.x; b128[2*p+1]=va.y-vb.y;
    }
#pragma unroll
    for (int j = 0; j < 4; j++){
        int kx = kbase + 2*j;
        float js = (j & 1) ? -1.0f : 1.0f;
        size_t b = ((size_t)(c*64 + kx))*512 + w0 + tw2;   // float2 units
#pragma unroll
        for (int p = 0; p < 4; p++){
            float2 tr = upk(aR[j][p]), ti = upk(aI[j][p]);
            if (par == 0){
                tr.x += x2v[2*p]   - x0v[2*p]   + js * a128[2*p];
                tr.y += x2v[2*p+1] - x0v[2*p+1] + js * a128[2*p+1];
            } else {
                tr.x += -x2v[2*p]   - x0v[2*p];
                tr.y += -x2v[2*p+1] - x0v[2*p+1];
                ti.x -= js * b128[2*p];
                ti.y -= js * b128[2*p+1];
            }
            *(float4*)&d_t1[b + 32*p] = make_float4(tr.x, ti.x, tr.y, ti.y);
        }
    }
}

// ============ K2 v4: packed complex, conflict-free interleaved ky mapping ============
__global__ void __launch_bounds__(256) k2_fwd_w(){
    __shared__ float2 sT[32][33];
    __shared__ u64 sC[32][65], sS[32][65];
    int tid = threadIdx.x, ck0 = blockIdx.x * 32, wbase = blockIdx.y * 256;
    int kyl = tid & 15, tck2 = (tid >> 4) * 2;
    u64 a1[2][4] = {}, a2[2][4] = {};
    for (int it = 0; it < 8; it++){
        int w0 = wbase + it * 32;
        __syncthreads();
        { int ckl = tid >> 3, wq = (tid & 7) * 4;
          const float4* tp = (const float4*)&d_t1[(size_t)(ck0+ckl)*512 + w0 + wq];
          float4 v0 = tp[0], v1 = tp[1];
          sT[wq+0][ckl] = make_float2(v0.x, v0.y);
          sT[wq+1][ckl] = make_float2(v0.z, v0.w);
          sT[wq+2][ckl] = make_float2(v1.x, v1.y);
          sT[wq+3][ckl] = make_float2(v1.z, v1.w); }
        { int ky = tid >> 2, w8 = (tid & 3) * 8;
          const float4* cp = (const float4*)&d_cF[ky*512 + w0 + w8];
          const float4* sp = (const float4*)&d_sF[ky*512 + w0 + w8];
          float4 c0 = cp[0], c1 = cp[1], s0 = sp[0], s1 = sp[1];
          sC[w8+0][ky]=pk(c0.x,c0.x); sC[w8+1][ky]=pk(c0.y,c0.y);
          sC[w8+2][ky]=pk(c0.z,c0.z); sC[w8+3][ky]=pk(c0.w,c0.w);
          sC[w8+4][ky]=pk(c1.x,c1.x); sC[w8+5][ky]=pk(c1.y,c1.y);
          sC[w8+6][ky]=pk(c1.z,c1.z); sC[w8+7][ky]=pk(c1.w,c1.w);
          sS[w8+0][ky]=pk(s0.x,s0.x); sS[w8+1][ky]=pk(s0.y,s0.y);
          sS[w8+2][ky]=pk(s0.z,s0.z); sS[w8+3][ky]=pk(s0.w,s0.w);
          sS[w8+4][ky]=pk(s1.x,s1.x); sS[w8+5][ky]=pk(s1.y,s1.y);
          sS[w8+6][ky]=pk(s1.z,s1.z); sS[w8+7][ky]=pk(s1.w,s1.w); }
        __syncthreads();
#pragma unroll 4
        for (int ww = 0; ww < 32; ww++){
            u64 T0 = *(const u64*)&sT[ww][tck2];
            u64 T1 = *(const u64*)&sT[ww][tck2+1];
#pragma unroll
            for (int q = 0; q < 4; q++){
                u64 C = sC[ww][kyl + 16*q], S = sS[ww][kyl + 16*q];
                a1[0][q] = fma2(T0, C, a1[0][q]);  a2[0][q] = fma2(T0, S, a2[0][q]);
                a1[1][q] = fma2(T1, C, a1[1][q]);  a2[1][q] = fma2(T1, S, a2[1][q]);
            }
        }
    }
#pragma unroll
    for (int j = 0; j < 2; j++){
        size_t row = (size_t)(ck0 + tck2 + j)*64;
#pragma unroll
        for (int q = 0; q < 4; q++){
            float2 v1 = upk(a1[j][q]), v2 = upk(a2[j][q]);
            d_xsp[blockIdx.y][row + kyl + 16*q] = make_float2(v1.x + v2.y, v1.y - v2.x);
        }
    }
}

// ============ K3 v2: 512 blocks, sums K2 partials during staging ============
__global__ void __launch_bounds__(256) k3_spectral(const float* __restrict__ wr_,
                                                   const float* __restrict__ wi_){
    __shared__ float2 sX[4096];
    int tid = threadIdx.x, kx = blockIdx.y;
    int o = blockIdx.x * 8 + (tid >> 5), ky2 = (tid & 31) * 2;
#pragma unroll
    for (int p = 0; p < 16; p++){
        int idx = tid + 256*p;
        size_t g = ((size_t)(idx >> 6))*4096 + kx*64 + (idx & 63);
        float2 a = d_xsp[0][g], b = d_xsp[1][g];
        sX[idx] = make_float2(a.x + b.x, a.y + b.y);
    }
    __syncthreads();
    float2 accR = {0,0}, accI = {0,0};
#pragma unroll 8
    for (int i = 0; i < 64; i++){
        size_t wb = ((size_t)((i*64 + o)*64 + kx))*64 + ky2;
        float2 wr = *(const float2*)&wr_[wb], wi = *(const float2*)&wi_[wb];
        float2 x0 = sX[i*64 + ky2], x1 = sX[i*64 + ky2 + 1];
        accR.x += x0.x*wr.x - x0.y*wi.x;  accI.x += x0.x*wi.x + x0.y*wr.x;
        accR.y += x1.x*wr.y - x1.y*wi.y;  accI.y += x1.x*wi.y + x1.y*wr.y;
    }
    size_t ob = (size_t)(o*64 + kx)*64 + ky2;
    *(float2*)&d_yfr[ob] = accR;
    *(float2*)&d_yfi[ob] = accI;
}

// ============ K4 (scalar): g[o,h,ky] = sum_kx yf e^{+i 2pi kx h/512} ============
__global__ void __launch_bounds__(256) k4_inv_h(){
    __shared__ float sYr[32][64], sYi[32][64], sC[32][64], sS[32][64];
    int tid = threadIdx.x, h0 = blockIdx.x * 64, o = blockIdx.y;
    int ky0 = (tid & 15) * 4, hb = (tid >> 4) * 4;
    float gR[4][4] = {}, gI[4][4] = {};
    for (int kx0 = 0; kx0 < 64; kx0 += 32){
        __syncthreads();
        { int k = tid >> 3, q8 = (tid & 7) * 8;
          const float4* yr = (const float4*)&d_yfr[(size_t)(o*64 + kx0 + k)*64 + q8];
          const float4* yi = (const float4*)&d_yfi[(size_t)(o*64 + kx0 + k)*64 + q8];
          *(float4*)&sYr[k][q8] = yr[0]; *(float4*)&sYr[k][q8+4] = yr[1];
          *(float4*)&sYi[k][q8] = yi[0]; *(float4*)&sYi[k][q8+4] = yi[1];
          const float4* cp = (const float4*)&d_cF[(kx0+k)*512 + h0 + q8];
          const float4* sp = (const float4*)&d_sF[(kx0+k)*512 + h0 + q8];
          *(float4*)&sC[k][q8] = cp[0]; *(float4*)&sC[k][q8+4] = cp[1];
          *(float4*)&sS[k][q8] = sp[0]; *(float4*)&sS[k][q8+4] = sp[1]; }
        __syncthreads();
#pragma unroll 4
        for (int k = 0; k < 32; k++){
            float yr[4], yi[4];
#pragma unroll
            for (int q = 0; q < 4; q++){ yr[q] = sYr[k][ky0+q]; yi[q] = sYi[k][ky0+q]; }
#pragma unroll
            for (int jh = 0; jh < 4; jh++){
                float cv = sC[k][hb+jh], sv = sS[k][hb+jh];
#pragma unroll
                for (int q = 0; q < 4; q++){
                    gR[jh][q] += yr[q]*cv - yi[q]*sv;
                    gI[jh][q] += yr[q]*sv + yi[q]*cv;
                }
            }
        }
    }
#pragma unroll
    for (int jh = 0; jh < 4; jh++){
        float2* dst = &d_g[((size_t)o*512 + h0 + hb + jh)*64 + ky0];
#pragma unroll
        for (int q = 0; q < 4; q++) dst[q] = make_float2(gR[jh][q], gI[jh][q]);
    }
}

// ============ K5 v2: (u,v)-packed conv + skip + bias + gelu ============
__global__ void __launch_bounds__(128, 4) k5_inv_w(const float* __restrict__ x,
        const float* __restrict__ b_conv, const float* __restrict__ w_skip,
        const float* __restrict__ b_skip, float* __restrict__ out){
    __shared__ float2 sG[16*64];
    __shared__ u64    sW[16*64];
    __shared__ float  sCv[16*512];

    int tid = threadIdx.x, o0 = blockIdx.x * 16, h = blockIdx.y;
    int og = tid >> 5, wg = tid & 31;

#pragma unroll
    for (int q = 0; q < 8; q++){
        int id = tid + 128*q, oo = id >> 6, k = id & 63;
        sG[id] = d_g[((size_t)(o0+oo)*512 + h)*64 + k];
        float wv = w_skip[(o0+oo)*64 + k];
        sW[id] = pk(wv, wv);
    }
    __syncthreads();

    u64 acc[4][8] = {};
#pragma unroll 2
    for (int ky = 0; ky < 64; ky++){
        u64 T[8];
#pragma unroll
        for (int p = 0; p < 8; p++)
            T[p] = *(const u64*)&d_csI[ky*512 + wg + 32*p];
#pragma unroll
        for (int oo = 0; oo < 4; oo++){
            u64 G = *(const u64*)&sG[(og*4 + oo)*64 + ky];
#pragma unroll
            for (int p = 0; p < 8; p++)
                acc[oo][p] = fma2(G, T[p], acc[oo][p]);
        }
    }
#pragma unroll
    for (int oo = 0; oo < 4; oo++){
        int o = og*4 + oo;
#pragma unroll
        for (int p = 0; p < 8; p++){
            int w = wg + 32*p;
            float2 uv = upk(acc[oo][p]);
            sCv[o*512 + w] = uv.x - uv.y;
            if (w) sCv[o*512 + 512 - w] = uv.x + uv.y;
        }
    }
    if (tid < 16){
        float s = 0.0f;
        for (int k = 0; k < 64; k++){
            float coef = (k == 0 ? 1.0f : 2.0f) * ((k & 1) ? -3.814697265625e-06f
                                                           :  3.814697265625e-06f);
            s += sG[tid*64 + k].x * coef;
        }
        sCv[tid*512 + 256] = s;
    }
    __syncthreads();

    u64 a0[16] = {}, a1[16] = {};
    const float* xh = x + (size_t)h*512 + 2*tid;
#pragma unroll 4
    for (int i = 0; i < 64; i++){
        u64 X0 = *(const u64*)&xh[(size_t)i*262144];
        u64 X1 = *(const u64*)&xh[(size_t)i*262144 + 256];
#pragma unroll
        for (int oo = 0; oo < 16; oo++){
            u64 W = sW[oo*64 + i];
            a0[oo] = fma2(W, X0, a0[oo]);
            a1[oo] = fma2(W, X1, a1[oo]);
        }
    }

#pragma unroll
    for (int oo = 0; oo < 16; oo++){
        int o = o0 + oo;
        float bias = b_conv[o] + b_skip[o];
        float2 c0 = *(const float2*)&sCv[oo*512 + 2*tid];
        float2 c1 = *(const float2*)&sCv[oo*512 + 256 + 2*tid];
        float2 s0 = upk(a0[oo]), s1 = upk(a1[oo]);
        float2 r0 = make_float2(gelu_t(s0.x + c0.x + bias), gelu_t(s0.y + c0.y + bias));
        float2 r1 = make_float2(gelu_t(s1.x + c1.x + bias), gelu_t(s1.y + c1.y + bias));
        size_t obase = (size_t)o*262144 + (size_t)h*512 + 2*tid;
        *(float2*)&out[obase]       = r0;
        *(float2*)&out[obase + 256] = r1;
    }
}

extern "C" void kernel_launch(void* const* d_in, const int* in_sizes, int n_in,
                              void* d_out, int out_size){
    const float* x      = (const float*)d_in[0];
    const float* w_real = (const float*)d_in[1];
    const float* w_imag = (const float*)d_in[2];
    const float* b_conv = (const float*)d_in[3];
    const float* w_skip = (const float*)d_in[4];
    const float* b_skip = (const float*)d_in[5];
    float* out = (float*)d_out;

    // capture slot (launch index 3) = k3_spectral
    k_tables<<<128, 256>>>();
    k1_fwd_h<<<dim3(4, 64), 256>>>(x);
    k2_fwd_w<<<dim3(128, 2), 256>>>();
    k3_spectral<<<dim3(8, 64), 256>>>(w_real, w_imag);
    k4_inv_h<<<dim3(8, 64), 256>>>();
    k5_inv_w<<<dim3(4, 512), 128>>>(x, b_conv, w_skip, b_skip, out);
}

// round 12
// speedup vs baseline: 1.2752x; 1.0059x over previous
#include <cuda_runtime.h>
#include <math.h>

typedef unsigned long long u64;
#define HSZ 512
#define NM  64

__device__ float  d_cF[NM*HSZ], d_sF[NM*HSZ], d_cI[NM*HSZ], d_sI[NM*HSZ];
__device__ float2 d_csI[NM*HSZ];               // interleaved (cI, sI) for K5
__device__ float2 d_t1[64*NM*HSZ];             // interleaved (tr, ti)
__device__ float2 d_xsp[2][64*NM*NM];          // K2 partial sums (w-halves)
__device__ float2 d_yf[64*NM*NM];              // interleaved (yr, yi)
__device__ float2 d_g[64*HSZ*NM];

__device__ __forceinline__ u64 pk(float lo, float hi){
    u64 r; asm("mov.b64 %0,{%1,%2};" : "=l"(r) : "f"(lo), "f"(hi)); return r; }
__device__ __forceinline__ u64 fma2(u64 a, u64 b, u64 c){
    u64 d; asm("fma.rn.f32x2 %0,%1,%2,%3;" : "=l"(d) : "l"(a), "l"(b), "l"(c)); return d; }
__device__ __forceinline__ float2 upk(u64 a){
    float2 f; asm("mov.b64 {%0,%1},%2;" : "=f"(f.x), "=f"(f.y) : "l"(a)); return f; }
__device__ __forceinline__ float gelu_t(float v){
    float u = 0.7978845608028654f * (v + 0.044715f * v * v * v), t;
    asm("tanh.approx.f32 %0,%1;" : "=f"(t) : "f"(u));
    return 0.5f * v * (1.0f + t); }

__global__ void k_tables(){
    int idx = blockIdx.x * 256 + threadIdx.x;
    int k = idx >> 9, n = idx & 511, t = (k * n) & 511;
    float s, c; sincosf((float)t * 0.012271846303085129f, &s, &c);
    d_cF[idx] = c; d_sF[idx] = s;
    float a = (k == 0 ? 1.0f : 2.0f) * (1.0f / 262144.0f);
    d_cI[idx] = a * c; d_sI[idx] = a * s;
    d_csI[idx] = make_float2(a * c, a * s);
}

// ============ K1 v3: quarter-wave double fold, parity-specialized warps ============
__global__ void __launch_bounds__(256, 2) k1_fwd_h(const float* __restrict__ x){
    __shared__ float sAe[16][128], sAo[16][128], sBe[16][128], sBo[16][128];
    __shared__ u64 sCt[16][64], sSn[16][64];
    int tid = threadIdx.x, c = blockIdx.y, w0 = blockIdx.x * 128;
    int tw2 = (tid & 15) * 2;
    int g = tid >> 4;
    int par = g >> 3;
    int kbase = (g & 7) * 8 + par;
    const float* xc = x + (size_t)c * 262144;

    u64 aR[4][4] = {}, aI[4][4] = {};
    for (int h0 = 0; h0 < 128; h0 += 16){
        __syncthreads();
        {   int r = tid >> 4, wq = (tid & 15) * 8;
            int hf = h0 + r;
            const float* pa = &xc[(size_t)hf*512 + w0 + wq];
            const float* pb = &xc[(size_t)((512 - hf) & 511)*512 + w0 + wq];
            const float* pc = &xc[(size_t)(256 - hf)*512 + w0 + wq];
            const float* pd = &xc[(size_t)(256 + hf)*512 + w0 + wq];
            float pe = (hf == 0) ? 0.0f : 1.0f;
#pragma unroll
            for (int q = 0; q < 2; q++){
                float4 va = *(const float4*)&pa[4*q];
                float4 vb = *(const float4*)&pb[4*q];
                float4 vc = *(const float4*)&pc[4*q];
                float4 vd = *(const float4*)&pd[4*q];
                float4 e4, o4, be4, bo4;
#pragma unroll
                for (int e = 0; e < 4; e++){
                    float fa = (&va.x)[e], fb = (&vb.x)[e];
                    float fc = (&vc.x)[e] * pe, fd = (&vd.x)[e] * pe;
                    float sab = fa + fb, dab = fa - fb;
                    float scd = fc + fd, dcd = fc - fd;
                    (&e4.x)[e]  = sab + scd;
                    (&o4.x)[e]  = sab - scd;
                    (&be4.x)[e] = dab - dcd;
                    (&bo4.x)[e] = dab + dcd;
                }
                *(float4*)&sAe[r][wq+4*q] = e4;
                *(float4*)&sAo[r][wq+4*q] = o4;
                *(float4*)&sBe[r][wq+4*q] = be4;
                *(float4*)&sBo[r][wq+4*q] = bo4;
            }
        }
        {   int kx = tid >> 2, hq = (tid & 3) * 4;
            float4 vc = *(const float4*)&d_cF[kx*512 + h0 + hq];
            float4 vs = *(const float4*)&d_sF[kx*512 + h0 + hq];
            sCt[hq+0][kx]=pk(vc.x,vc.x); sCt[hq+1][kx]=pk(vc.y,vc.y);
            sCt[hq+2][kx]=pk(vc.z,vc.z); sCt[hq+3][kx]=pk(vc.w,vc.w);
            sSn[hq+0][kx]=pk(-vs.x,-vs.x); sSn[hq+1][kx]=pk(-vs.y,-vs.y);
            sSn[hq+2][kx]=pk(-vs.z,-vs.z); sSn[hq+3][kx]=pk(-vs.w,-vs.w);
        }
        __syncthreads();
        const float* rowA = par ? &sAo[0][0] : &sAe[0][0];
        const float* rowB = par ? &sBo[0][0] : &sBe[0][0];
#pragma unroll 4
        for (int hh = 0; hh < 16; hh++){
            u64 A[4], B[4];
#pragma unroll
            for (int p = 0; p < 4; p++){
                A[p] = *(const u64*)&rowA[hh*128 + tw2 + 32*p];
                B[p] = *(const u64*)&rowB[hh*128 + tw2 + 32*p];
            }
#pragma unroll
            for (int j = 0; j < 4; j++){
                u64 C = sCt[hh][kbase + 2*j], S = sSn[hh][kbase + 2*j];
#pragma unroll
                for (int p = 0; p < 4; p++){
                    aR[j][p] = fma2(C, A[p], aR[j][p]);
                    aI[j][p] = fma2(S, B[p], aI[j][p]);
                }
            }
        }
    }

    float x0v[8], x2v[8], a128[8], b128[8];
#pragma unroll
    for (int p = 0; p < 4; p++){
        float2 v0 = *(const float2*)&xc[w0 + tw2 + 32*p];
        float2 v2 = *(const float2*)&xc[(size_t)256*512 + w0 + tw2 + 32*p];
        float2 va = *(const float2*)&xc[(size_t)128*512 + w0 + tw2 + 32*p];
        float2 vb = *(const float2*)&xc[(size_t)384*512 + w0 + tw2 + 32*p];
        x0v[2*p]=v0.x; x0v[2*p+1]=v0.y;
        x2v[2*p]=v2.x; x2v[2*p+1]=v2.y;
        a128[2*p]=va.x+vb.x; a128[2*p+1]=va.y+vb.y;
        b128[2*p]=va.x-vb.x; b128[2*p+1]=va.y-vb.y;
    }
#pragma unroll
    for (int j = 0; j < 4; j++){
        int kx = kbase + 2*j;
        float js = (j & 1) ? -1.0f : 1.0f;
        size_t b = ((size_t)(c*64 + kx))*512 + w0 + tw2;
#pragma unroll
        for (int p = 0; p < 4; p++){
            float2 tr = upk(aR[j][p]), ti = upk(aI[j][p]);
            if (par == 0){
                tr.x += x2v[2*p]   - x0v[2*p]   + js * a128[2*p];
                tr.y += x2v[2*p+1] - x0v[2*p+1] + js * a128[2*p+1];
            } else {
                tr.x += -x2v[2*p]   - x0v[2*p];
                tr.y += -x2v[2*p+1] - x0v[2*p+1];
                ti.x -= js * b128[2*p];
                ti.y -= js * b128[2*p+1];
            }
            *(float4*)&d_t1[b + 32*p] = make_float4(tr.x, ti.x, tr.y, ti.y);
        }
    }
}

// ============ K2 v4: packed complex, conflict-free interleaved ky mapping ============
__global__ void __launch_bounds__(256) k2_fwd_w(){
    __shared__ float2 sT[32][33];
    __shared__ u64 sC[32][65], sS[32][65];
    int tid = threadIdx.x, ck0 = blockIdx.x * 32, wbase = blockIdx.y * 256;
    int kyl = tid & 15, tck2 = (tid >> 4) * 2;
    u64 a1[2][4] = {}, a2[2][4] = {};
    for (int it = 0; it < 8; it++){
        int w0 = wbase + it * 32;
        __syncthreads();
        { int ckl = tid >> 3, wq = (tid & 7) * 4;
          const float4* tp = (const float4*)&d_t1[(size_t)(ck0+ckl)*512 + w0 + wq];
          float4 v0 = tp[0], v1 = tp[1];
          sT[wq+0][ckl] = make_float2(v0.x, v0.y);
          sT[wq+1][ckl] = make_float2(v0.z, v0.w);
          sT[wq+2][ckl] = make_float2(v1.x, v1.y);
          sT[wq+3][ckl] = make_float2(v1.z, v1.w); }
        { int ky = tid >> 2, w8 = (tid & 3) * 8;
          const float4* cp = (const float4*)&d_cF[ky*512 + w0 + w8];
          const float4* sp = (const float4*)&d_sF[ky*512 + w0 + w8];
          float4 c0 = cp[0], c1 = cp[1], s0 = sp[0], s1 = sp[1];
          sC[w8+0][ky]=pk(c0.x,c0.x); sC[w8+1][ky]=pk(c0.y,c0.y);
          sC[w8+2][ky]=pk(c0.z,c0.z); sC[w8+3][ky]=pk(c0.w,c0.w);
          sC[w8+4][ky]=pk(c1.x,c1.x); sC[w8+5][ky]=pk(c1.y,c1.y);
          sC[w8+6][ky]=pk(c1.z,c1.z); sC[w8+7][ky]=pk(c1.w,c1.w);
          sS[w8+0][ky]=pk(s0.x,s0.x); sS[w8+1][ky]=pk(s0.y,s0.y);
          sS[w8+2][ky]=pk(s0.z,s0.z); sS[w8+3][ky]=pk(s0.w,s0.w);
          sS[w8+4][ky]=pk(s1.x,s1.x); sS[w8+5][ky]=pk(s1.y,s1.y);
          sS[w8+6][ky]=pk(s1.z,s1.z); sS[w8+7][ky]=pk(s1.w,s1.w); }
        __syncthreads();
#pragma unroll 4
        for (int ww = 0; ww < 32; ww++){
            u64 T0 = *(const u64*)&sT[ww][tck2];
            u64 T1 = *(const u64*)&sT[ww][tck2+1];
#pragma unroll
            for (int q = 0; q < 4; q++){
                u64 C = sC[ww][kyl + 16*q], S = sS[ww][kyl + 16*q];
                a1[0][q] = fma2(T0, C, a1[0][q]);  a2[0][q] = fma2(T0, S, a2[0][q]);
                a1[1][q] = fma2(T1, C, a1[1][q]);  a2[1][q] = fma2(T1, S, a2[1][q]);
            }
        }
    }
#pragma unroll
    for (int j = 0; j < 2; j++){
        size_t row = (size_t)(ck0 + tck2 + j)*64;
#pragma unroll
        for (int q = 0; q < 4; q++){
            float2 v1 = upk(a1[j][q]), v2 = upk(a2[j][q]);
            d_xsp[blockIdx.y][row + kyl + 16*q] = make_float2(v1.x + v2.y, v1.y - v2.x);
        }
    }
}

// ============ K3 v3: 512 blocks, interleaved output ============
__global__ void __launch_bounds__(256) k3_spectral(const float* __restrict__ wr_,
                                                   const float* __restrict__ wi_){
    __shared__ float2 sX[4096];
    int tid = threadIdx.x, kx = blockIdx.y;
    int o = blockIdx.x * 8 + (tid >> 5), ky2 = (tid & 31) * 2;
#pragma unroll
    for (int p = 0; p < 16; p++){
        int idx = tid + 256*p;
        size_t g = ((size_t)(idx >> 6))*4096 + kx*64 + (idx & 63);
        float2 a = d_xsp[0][g], b = d_xsp[1][g];
        sX[idx] = make_float2(a.x + b.x, a.y + b.y);
    }
    __syncthreads();
    float2 accR = {0,0}, accI = {0,0};
#pragma unroll 8
    for (int i = 0; i < 64; i++){
        size_t wb = ((size_t)((i*64 + o)*64 + kx))*64 + ky2;
        float2 wr = *(const float2*)&wr_[wb], wi = *(const float2*)&wi_[wb];
        float2 x0 = sX[i*64 + ky2], x1 = sX[i*64 + ky2 + 1];
        accR.x += x0.x*wr.x - x0.y*wi.x;  accI.x += x0.x*wi.x + x0.y*wr.x;
        accR.y += x1.x*wr.y - x1.y*wi.y;  accI.y += x1.x*wi.y + x1.y*wr.y;
    }
    size_t ob = (size_t)(o*64 + kx)*64 + ky2;      // float2 units
    *(float4*)&d_yf[ob] = make_float4(accR.x, accI.x, accR.y, accI.y);
}

// ============ K4 v2: packed complex, conflict-free interleaved ============
// acc1 = sum (yr,yi)(c,c), acc2 = sum (yr,yi)(s,s)
// gr = acc1.x - acc2.y ; gi = acc1.y + acc2.x
__global__ void __launch_bounds__(256, 2) k4_inv_h(){
    __shared__ float2 sY[32][64];            // [kx][ky] natural pairs
    __shared__ u64 sC[32][64], sS[32][64];   // [kx][h] dup pairs
    int tid = threadIdx.x, h0 = blockIdx.x * 64, o = blockIdx.y;
    int hs = tid >> 3, kyl = tid & 7;        // h = 2*hs+jh, ky = kyl + 8q
    u64 a1[2][8] = {}, a2[2][8] = {};
    for (int kx0 = 0; kx0 < 64; kx0 += 32){
        __syncthreads();
        {   int kxl = tid >> 3, kq = (tid & 7) * 8;
            const float4* yp = (const float4*)&d_yf[(size_t)(o*64 + kx0 + kxl)*64 + kq];
            float4 v0 = yp[0], v1 = yp[1], v2 = yp[2], v3 = yp[3];
            *(float4*)&sY[kxl][kq]   = v0;
            *(float4*)&sY[kxl][kq+2] = v1;
            *(float4*)&sY[kxl][kq+4] = v2;
            *(float4*)&sY[kxl][kq+6] = v3;
        }
        {   int kxl = tid >> 3, hq = (tid & 7) * 8;
            const float4* cp = (const float4*)&d_cF[(kx0+kxl)*512 + h0 + hq];
            const float4* sp = (const float4*)&d_sF[(kx0+kxl)*512 + h0 + hq];
            float4 c0 = cp[0], c1 = cp[1], s0 = sp[0], s1 = sp[1];
            sC[kxl][hq+0]=pk(c0.x,c0.x); sC[kxl][hq+1]=pk(c0.y,c0.y);
            sC[kxl][hq+2]=pk(c0.z,c0.z); sC[kxl][hq+3]=pk(c0.w,c0.w);
            sC[kxl][hq+4]=pk(c1.x,c1.x); sC[kxl][hq+5]=pk(c1.y,c1.y);
            sC[kxl][hq+6]=pk(c1.z,c1.z); sC[kxl][hq+7]=pk(c1.w,c1.w);
            sS[kxl][hq+0]=pk(s0.x,s0.x); sS[kxl][hq+1]=pk(s0.y,s0.y);
            sS[kxl][hq+2]=pk(s0.z,s0.z); sS[kxl][hq+3]=pk(s0.w,s0.w);
            sS[kxl][hq+4]=pk(s1.x,s1.x); sS[kxl][hq+5]=pk(s1.y,s1.y);
            sS[kxl][hq+6]=pk(s1.z,s1.z); sS[kxl][hq+7]=pk(s1.w,s1.w);
        }
        __syncthreads();
#pragma unroll 4
        for (int k = 0; k < 32; k++){
            u64 Y[8];
#pragma unroll
            for (int q = 0; q < 8; q++)
                Y[q] = *(const u64*)&sY[k][kyl + 8*q];
#pragma unroll
            for (int jh = 0; jh < 2; jh++){
                u64 C = sC[k][2*hs + jh], S = sS[k][2*hs + jh];
#pragma unroll
                for (int q = 0; q < 8; q++){
                    a1[jh][q] = fma2(Y[q], C, a1[jh][q]);
                    a2[jh][q] = fma2(Y[q], S, a2[jh][q]);
                }
            }
        }
    }
#pragma unroll
    for (int jh = 0; jh < 2; jh++){
        int h = h0 + 2*hs + jh;
#pragma unroll
        for (int q = 0; q < 8; q++){
            float2 v1 = upk(a1[jh][q]), v2 = upk(a2[jh][q]);
            d_g[((size_t)o*512 + h)*64 + kyl + 8*q] =
                make_float2(v1.x - v2.y, v1.y + v2.x);
        }
    }
}

// ============ K5 v2: (u,v)-packed conv + skip + bias + gelu ============
__global__ void __launch_bounds__(128, 4) k5_inv_w(const float* __restrict__ x,
        const float* __restrict__ b_conv, const float* __restrict__ w_skip,
        const float* __restrict__ b_skip, float* __restrict__ out){
    __shared__ float2 sG[16*64];
    __shared__ u64    sW[16*64];
    __shared__ float  sCv[16*512];

    int tid = threadIdx.x, o0 = blockIdx.x * 16, h = blockIdx.y;
    int og = tid >> 5, wg = tid & 31;

#pragma unroll
    for (int q = 0; q < 8; q++){
        int id = tid + 128*q, oo = id >> 6, k = id & 63;
        sG[id] = d_g[((size_t)(o0+oo)*512 + h)*64 + k];
        float wv = w_skip[(o0+oo)*64 + k];
        sW[id] = pk(wv, wv);
    }
    __syncthreads();

    u64 acc[4][8] = {};
#pragma unroll 2
    for (int ky = 0; ky < 64; ky++){
        u64 T[8];
#pragma unroll
        for (int p = 0; p < 8; p++)
            T[p] = *(const u64*)&d_csI[ky*512 + wg + 32*p];
#pragma unroll
        for (int oo = 0; oo < 4; oo++){
            u64 G = *(const u64*)&sG[(og*4 + oo)*64 + ky];
#pragma unroll
            for (int p = 0; p < 8; p++)
                acc[oo][p] = fma2(G, T[p], acc[oo][p]);
        }
    }
#pragma unroll
    for (int oo = 0; oo < 4; oo++){
        int o = og*4 + oo;
#pragma unroll
        for (int p = 0; p < 8; p++){
            int w = wg + 32*p;
            float2 uv = upk(acc[oo][p]);
            sCv[o*512 + w] = uv.x - uv.y;
            if (w) sCv[o*512 + 512 - w] = uv.x + uv.y;
        }
    }
    if (tid < 16){
        float s = 0.0f;
        for (int k = 0; k < 64; k++){
            float coef = (k == 0 ? 1.0f : 2.0f) * ((k & 1) ? -3.814697265625e-06f
                                                           :  3.814697265625e-06f);
            s += sG[tid*64 + k].x * coef;
        }
        sCv[tid*512 + 256] = s;
    }
    __syncthreads();

    u64 a0[16] = {}, a1[16] = {};
    const float* xh = x + (size_t)h*512 + 2*tid;
#pragma unroll 4
    for (int i = 0; i < 64; i++){
        u64 X0 = *(const u64*)&xh[(size_t)i*262144];
        u64 X1 = *(const u64*)&xh[(size_t)i*262144 + 256];
#pragma unroll
        for (int oo = 0; oo < 16; oo++){
            u64 W = sW[oo*64 + i];
            a0[oo] = fma2(W, X0, a0[oo]);
            a1[oo] = fma2(W, X1, a1[oo]);
        }
    }

#pragma unroll
    for (int oo = 0; oo < 16; oo++){
        int o = o0 + oo;
        float bias = b_conv[o] + b_skip[o];
        float2 c0 = *(const float2*)&sCv[oo*512 + 2*tid];
        float2 c1 = *(const float2*)&sCv[oo*512 + 256 + 2*tid];
        float2 s0 = upk(a0[oo]), s1 = upk(a1[oo]);
        float2 r0 = make_float2(gelu_t(s0.x + c0.x + bias), gelu_t(s0.y + c0.y + bias));
        float2 r1 = make_float2(gelu_t(s1.x + c1.x + bias), gelu_t(s1.y + c1.y + bias));
        size_t obase = (size_t)o*262144 + (size_t)h*512 + 2*tid;
        *(float2*)&out[obase]       = r0;
        *(float2*)&out[obase + 256] = r1;
    }
}

extern "C" void kernel_launch(void* const* d_in, const int* in_sizes, int n_in,
                              void* d_out, int out_size){
    const float* x      = (const float*)d_in[0];
    const float* w_real = (const float*)d_in[1];
    const float* w_imag = (const float*)d_in[2];
    const float* b_conv = (const float*)d_in[3];
    const float* w_skip = (const float*)d_in[4];
    const float* b_skip = (const float*)d_in[5];
    float* out = (float*)d_out;

    // capture slot (launch index 3) = k1_fwd_h (2 pad tables)
    k_tables<<<128, 256>>>();
    k_tables<<<128, 256>>>();
    k_tables<<<128, 256>>>();
    k1_fwd_h<<<dim3(4, 64), 256>>>(x);
    k2_fwd_w<<<dim3(128, 2), 256>>>();
    k3_spectral<<<dim3(8, 64), 256>>>(w_real, w_imag);
    k4_inv_h<<<dim3(8, 64), 256>>>();
    k5_inv_w<<<dim3(4, 512), 128>>>(x, b_conv, w_skip, b_skip, out);
}

// round 13
// speedup vs baseline: 1.2759x; 1.0006x over previous
#include <cuda_runtime.h>
#include <math.h>

typedef unsigned long long u64;
#define HSZ 512
#define NM  64

__device__ float  d_cF[NM*HSZ], d_sF[NM*HSZ], d_cI[NM*HSZ], d_sI[NM*HSZ];
__device__ float2 d_csI[NM*HSZ];               // interleaved (cI, sI) for K5
__device__ float2 d_t1[64*NM*HSZ];             // interleaved (tr, ti)
__device__ float2 d_xsp[2][64*NM*NM];          // K2 partial sums (w-halves)
__device__ float2 d_yf[64*NM*NM];              // interleaved (yr, yi)
__device__ float2 d_g[64*HSZ*NM];

__device__ __forceinline__ u64 pk(float lo, float hi){
    u64 r; asm("mov.b64 %0,{%1,%2};" : "=l"(r) : "f"(lo), "f"(hi)); return r; }
__device__ __forceinline__ u64 fma2(u64 a, u64 b, u64 c){
    u64 d; asm("fma.rn.f32x2 %0,%1,%2,%3;" : "=l"(d) : "l"(a), "l"(b), "l"(c)); return d; }
__device__ __forceinline__ float2 upk(u64 a){
    float2 f; asm("mov.b64 {%0,%1},%2;" : "=f"(f.x), "=f"(f.y) : "l"(a)); return f; }
__device__ __forceinline__ float gelu_t(float v){
    float u = 0.7978845608028654f * (v + 0.044715f * v * v * v), t;
    asm("tanh.approx.f32 %0,%1;" : "=f"(t) : "f"(u));
    return 0.5f * v * (1.0f + t); }

__global__ void k_tables(){
    int idx = blockIdx.x * 256 + threadIdx.x;
    int k = idx >> 9, n = idx & 511, t = (k * n) & 511;
    float s, c; sincosf((float)t * 0.012271846303085129f, &s, &c);
    d_cF[idx] = c; d_sF[idx] = s;
    float a = (k == 0 ? 1.0f : 2.0f) * (1.0f / 262144.0f);
    d_cI[idx] = a * c; d_sI[idx] = a * s;
    d_csI[idx] = make_float2(a * c, a * s);
}

// ============ K1 v4: double fold, w-tile 64, 4 CTA/SM, single wave ============
__global__ void __launch_bounds__(256, 4) k1_fwd_h(const float* __restrict__ x){
    __shared__ float sAe[16][64], sAo[16][64], sBe[16][64], sBo[16][64];
    __shared__ u64 sCt[16][65], sSn[16][65];
    int tid = threadIdx.x, c = blockIdx.y, w0 = blockIdx.x * 64;
    int tw2 = (tid & 15) * 2;
    int g = tid >> 4;
    int par = g >> 3;
    int kbase = (g & 7) * 8 + par;
    const float* xc = x + (size_t)c * 262144;

    u64 aR[4][2] = {}, aI[4][2] = {};
    for (int h0 = 0; h0 < 128; h0 += 16){
        __syncthreads();
        {   int r = tid >> 4, wq = (tid & 15) * 4;
            int hf = h0 + r;
            const float* pa = &xc[(size_t)hf*512 + w0 + wq];
            const float* pb = &xc[(size_t)((512 - hf) & 511)*512 + w0 + wq];
            const float* pc = &xc[(size_t)(256 - hf)*512 + w0 + wq];
            const float* pd = &xc[(size_t)(256 + hf)*512 + w0 + wq];
            float pe = (hf == 0) ? 0.0f : 1.0f;
            float4 va = *(const float4*)pa;
            float4 vb = *(const float4*)pb;
            float4 vc = *(const float4*)pc;
            float4 vd = *(const float4*)pd;
            float4 e4, o4, be4, bo4;
#pragma unroll
            for (int e = 0; e < 4; e++){
                float fa = (&va.x)[e], fb = (&vb.x)[e];
                float fc = (&vc.x)[e] * pe, fd = (&vd.x)[e] * pe;
                float sab = fa + fb, dab = fa - fb;
                float scd = fc + fd, dcd = fc - fd;
                (&e4.x)[e]  = sab + scd;
                (&o4.x)[e]  = sab - scd;
                (&be4.x)[e] = dab - dcd;
                (&bo4.x)[e] = dab + dcd;
            }
            *(float4*)&sAe[r][wq] = e4;
            *(float4*)&sAo[r][wq] = o4;
            *(float4*)&sBe[r][wq] = be4;
            *(float4*)&sBo[r][wq] = bo4;
        }
        {   int kx = tid >> 2, hq = (tid & 3) * 4;
            float4 vc = *(const float4*)&d_cF[kx*512 + h0 + hq];
            float4 vs = *(const float4*)&d_sF[kx*512 + h0 + hq];
            sCt[hq+0][kx]=pk(vc.x,vc.x); sCt[hq+1][kx]=pk(vc.y,vc.y);
            sCt[hq+2][kx]=pk(vc.z,vc.z); sCt[hq+3][kx]=pk(vc.w,vc.w);
            sSn[hq+0][kx]=pk(-vs.x,-vs.x); sSn[hq+1][kx]=pk(-vs.y,-vs.y);
            sSn[hq+2][kx]=pk(-vs.z,-vs.z); sSn[hq+3][kx]=pk(-vs.w,-vs.w);
        }
        __syncthreads();
        const float* rowA = par ? &sAo[0][0] : &sAe[0][0];
        const float* rowB = par ? &sBo[0][0] : &sBe[0][0];
#pragma unroll 4
        for (int hh = 0; hh < 16; hh++){
            u64 A0 = *(const u64*)&rowA[hh*64 + tw2];
            u64 A1 = *(const u64*)&rowA[hh*64 + tw2 + 32];
            u64 B0 = *(const u64*)&rowB[hh*64 + tw2];
            u64 B1 = *(const u64*)&rowB[hh*64 + tw2 + 32];
#pragma unroll
            for (int j = 0; j < 4; j++){
                u64 C = sCt[hh][kbase + 2*j], S = sSn[hh][kbase + 2*j];
                aR[j][0] = fma2(C, A0, aR[j][0]);
                aR[j][1] = fma2(C, A1, aR[j][1]);
                aI[j][0] = fma2(S, B0, aI[j][0]);
                aI[j][1] = fma2(S, B1, aI[j][1]);
            }
        }
    }

    // epilogue corrections
    float x0v[4], x2v[4], a128[4], b128[4];
#pragma unroll
    for (int p = 0; p < 2; p++){
        float2 v0 = *(const float2*)&xc[w0 + tw2 + 32*p];
        float2 v2 = *(const float2*)&xc[(size_t)256*512 + w0 + tw2 + 32*p];
        float2 va = *(const float2*)&xc[(size_t)128*512 + w0 + tw2 + 32*p];
        float2 vb = *(const float2*)&xc[(size_t)384*512 + w0 + tw2 + 32*p];
        x0v[2*p]=v0.x; x0v[2*p+1]=v0.y;
        x2v[2*p]=v2.x; x2v[2*p+1]=v2.y;
        a128[2*p]=va.x+vb.x; a128[2*p+1]=va.y+vb.y;
        b128[2*p]=va.x-vb.x; b128[2*p+1]=va.y-vb.y;
    }
#pragma unroll
    for (int j = 0; j < 4; j++){
        int kx = kbase + 2*j;
        float js = (j & 1) ? -1.0f : 1.0f;
        size_t b = ((size_t)(c*64 + kx))*512 + w0 + tw2;
#pragma unroll
        for (int p = 0; p < 2; p++){
            float2 tr = upk(aR[j][p]), ti = upk(aI[j][p]);
            if (par == 0){
                tr.x += x2v[2*p]   - x0v[2*p]   + js * a128[2*p];
                tr.y += x2v[2*p+1] - x0v[2*p+1] + js * a128[2*p+1];
            } else {
                tr.x += -x2v[2*p]   - x0v[2*p];
                tr.y += -x2v[2*p+1] - x0v[2*p+1];
                ti.x -= js * b128[2*p];
                ti.y -= js * b128[2*p+1];
            }
            *(float4*)&d_t1[b + 32*p] = make_float4(tr.x, ti.x, tr.y, ti.y);
        }
    }
}

// ============ K2 v4: packed complex, conflict-free interleaved ky mapping ============
__global__ void __launch_bounds__(256) k2_fwd_w(){
    __shared__ float2 sT[32][33];
    __shared__ u64 sC[32][65], sS[32][65];
    int tid = threadIdx.x, ck0 = blockIdx.x * 32, wbase = blockIdx.y * 256;
    int kyl = tid & 15, tck2 = (tid >> 4) * 2;
    u64 a1[2][4] = {}, a2[2][4] = {};
    for (int it = 0; it < 8; it++){
        int w0 = wbase + it * 32;
        __syncthreads();
        { int ckl = tid >> 3, wq = (tid & 7) * 4;
          const float4* tp = (const float4*)&d_t1[(size_t)(ck0+ckl)*512 + w0 + wq];
          float4 v0 = tp[0], v1 = tp[1];
          sT[wq+0][ckl] = make_float2(v0.x, v0.y);
          sT[wq+1][ckl] = make_float2(v0.z, v0.w);
          sT[wq+2][ckl] = make_float2(v1.x, v1.y);
          sT[wq+3][ckl] = make_float2(v1.z, v1.w); }
        { int ky = tid >> 2, w8 = (tid & 3) * 8;
          const float4* cp = (const float4*)&d_cF[ky*512 + w0 + w8];
          const float4* sp = (const float4*)&d_sF[ky*512 + w0 + w8];
          float4 c0 = cp[0], c1 = cp[1], s0 = sp[0], s1 = sp[1];
          sC[w8+0][ky]=pk(c0.x,c0.x); sC[w8+1][ky]=pk(c0.y,c0.y);
          sC[w8+2][ky]=pk(c0.z,c0.z); sC[w8+3][ky]=pk(c0.w,c0.w);
          sC[w8+4][ky]=pk(c1.x,c1.x); sC[w8+5][ky]=pk(c1.y,c1.y);
          sC[w8+6][ky]=pk(c1.z,c1.z); sC[w8+7][ky]=pk(c1.w,c1.w);
          sS[w8+0][ky]=pk(s0.x,s0.x); sS[w8+1][ky]=pk(s0.y,s0.y);
          sS[w8+2][ky]=pk(s0.z,s0.z); sS[w8+3][ky]=pk(s0.w,s0.w);
          sS[w8+4][ky]=pk(s1.x,s1.x); sS[w8+5][ky]=pk(s1.y,s1.y);
          sS[w8+6][ky]=pk(s1.z,s1.z); sS[w8+7][ky]=pk(s1.w,s1.w); }
        __syncthreads();
#pragma unroll 4
        for (int ww = 0; ww < 32; ww++){
            u64 T0 = *(const u64*)&sT[ww][tck2];
            u64 T1 = *(const u64*)&sT[ww][tck2+1];
#pragma unroll
            for (int q = 0; q < 4; q++){
                u64 C = sC[ww][kyl + 16*q], S = sS[ww][kyl + 16*q];
                a1[0][q] = fma2(T0, C, a1[0][q]);  a2[0][q] = fma2(T0, S, a2[0][q]);
                a1[1][q] = fma2(T1, C, a1[1][q]);  a2[1][q] = fma2(T1, S, a2[1][q]);
            }
        }
    }
#pragma unroll
    for (int j = 0; j < 2; j++){
        size_t row = (size_t)(ck0 + tck2 + j)*64;
#pragma unroll
        for (int q = 0; q < 4; q++){
            float2 v1 = upk(a1[j][q]), v2 = upk(a2[j][q]);
            d_xsp[blockIdx.y][row + kyl + 16*q] = make_float2(v1.x + v2.y, v1.y - v2.x);
        }
    }
}

// ============ K3 v4: 1024 blocks (o-tile 4, 128 threads) ============
__global__ void __launch_bounds__(128) k3_spectral(const float* __restrict__ wr_,
                                                   const float* __restrict__ wi_){
    __shared__ float2 sX[4096];
    int tid = threadIdx.x, kx = blockIdx.y;
    int o = blockIdx.x * 4 + (tid >> 5), ky2 = (tid & 31) * 2;
#pragma unroll
    for (int p = 0; p < 32; p++){
        int idx = tid + 128*p;
        size_t g = ((size_t)(idx >> 6))*4096 + kx*64 + (idx & 63);
        float2 a = d_xsp[0][g], b = d_xsp[1][g];
        sX[idx] = make_float2(a.x + b.x, a.y + b.y);
    }
    __syncthreads();
    float2 accR = {0,0}, accI = {0,0};
#pragma unroll 8
    for (int i = 0; i < 64; i++){
        size_t wb = ((size_t)((i*64 + o)*64 + kx))*64 + ky2;
        float2 wr = *(const float2*)&wr_[wb], wi = *(const float2*)&wi_[wb];
        float2 x0 = sX[i*64 + ky2], x1 = sX[i*64 + ky2 + 1];
        accR.x += x0.x*wr.x - x0.y*wi.x;  accI.x += x0.x*wi.x + x0.y*wr.x;
        accR.y += x1.x*wr.y - x1.y*wi.y;  accI.y += x1.x*wi.y + x1.y*wr.y;
    }
    size_t ob = (size_t)(o*64 + kx)*64 + ky2;
    *(float4*)&d_yf[ob] = make_float4(accR.x, accI.x, accR.y, accI.y);
}

// ============ K4 v2: packed complex, conflict-free interleaved ============
__global__ void __launch_bounds__(256, 2) k4_inv_h(){
    __shared__ float2 sY[32][64];
    __shared__ u64 sC[32][64], sS[32][64];
    int tid = threadIdx.x, h0 = blockIdx.x * 64, o = blockIdx.y;
    int hs = tid >> 3, kyl = tid & 7;
    u64 a1[2][8] = {}, a2[2][8] = {};
    for (int kx0 = 0; kx0 < 64; kx0 += 32){
        __syncthreads();
        {   int kxl = tid >> 3, kq = (tid & 7) * 8;
            const float4* yp = (const float4*)&d_yf[(size_t)(o*64 + kx0 + kxl)*64 + kq];
            float4 v0 = yp[0], v1 = yp[1], v2 = yp[2], v3 = yp[3];
            *(float4*)&sY[kxl][kq]   = v0;
            *(float4*)&sY[kxl][kq+2] = v1;
            *(float4*)&sY[kxl][kq+4] = v2;
            *(float4*)&sY[kxl][kq+6] = v3;
        }
        {   int kxl = tid >> 3, hq = (tid & 7) * 8;
            const float4* cp = (const float4*)&d_cF[(kx0+kxl)*512 + h0 + hq];
            const float4* sp = (const float4*)&d_sF[(kx0+kxl)*512 + h0 + hq];
            float4 c0 = cp[0], c1 = cp[1], s0 = sp[0], s1 = sp[1];
            sC[kxl][hq+0]=pk(c0.x,c0.x); sC[kxl][hq+1]=pk(c0.y,c0.y);
            sC[kxl][hq+2]=pk(c0.z,c0.z); sC[kxl][hq+3]=pk(c0.w,c0.w);
            sC[kxl][hq+4]=pk(c1.x,c1.x); sC[kxl][hq+5]=pk(c1.y,c1.y);
            sC[kxl][hq+6]=pk(c1.z,c1.z); sC[kxl][hq+7]=pk(c1.w,c1.w);
            sS[kxl][hq+0]=pk(s0.x,s0.x); sS[kxl][hq+1]=pk(s0.y,s0.y);
            sS[kxl][hq+2]=pk(s0.z,s0.z); sS[kxl][hq+3]=pk(s0.w,s0.w);
            sS[kxl][hq+4]=pk(s1.x,s1.x); sS[kxl][hq+5]=pk(s1.y,s1.y);
            sS[kxl][hq+6]=pk(s1.z,s1.z); sS[kxl][hq+7]=pk(s1.w,s1.w);
        }
        __syncthreads();
#pragma unroll 4
        for (int k = 0; k < 32; k++){
            u64 Y[8];
#pragma unroll
            for (int q = 0; q < 8; q++)
                Y[q] = *(const u64*)&sY[k][kyl + 8*q];
#pragma unroll
            for (int jh = 0; jh < 2; jh++){
                u64 C = sC[k][2*hs + jh], S = sS[k][2*hs + jh];
#pragma unroll
                for (int q = 0; q < 8; q++){
                    a1[jh][q] = fma2(Y[q], C, a1[jh][q]);
                    a2[jh][q] = fma2(Y[q], S, a2[jh][q]);
                }
            }
        }
    }
#pragma unroll
    for (int jh = 0; jh < 2; jh++){
        int h = h0 + 2*hs + jh;
#pragma unroll
        for (int q = 0; q < 8; q++){
            float2 v1 = upk(a1[jh][q]), v2 = upk(a2[jh][q]);
            d_g[((size_t)o*512 + h)*64 + kyl + 8*q] =
                make_float2(v1.x - v2.y, v1.y + v2.x);
        }
    }
}

// ============ K5 v2: (u,v)-packed conv + skip + bias + gelu ============
__global__ void __launch_bounds__(128, 4) k5_inv_w(const float* __restrict__ x,
        const float* __restrict__ b_conv, const float* __restrict__ w_skip,
        const float* __restrict__ b_skip, float* __restrict__ out){
    __shared__ float2 sG[16*64];
    __shared__ u64    sW[16*64];
    __shared__ float  sCv[16*512];

    int tid = threadIdx.x, o0 = blockIdx.x * 16, h = blockIdx.y;
    int og = tid >> 5, wg = tid & 31;

#pragma unroll
    for (int q = 0; q < 8; q++){
        int id = tid + 128*q, oo = id >> 6, k = id & 63;
        sG[id] = d_g[((size_t)(o0+oo)*512 + h)*64 + k];
        float wv = w_skip[(o0+oo)*64 + k];
        sW[id] = pk(wv, wv);
    }
    __syncthreads();

    u64 acc[4][8] = {};
#pragma unroll 2
    for (int ky = 0; ky < 64; ky++){
        u64 T[8];
#pragma unroll
        for (int p = 0; p < 8; p++)
            T[p] = *(const u64*)&d_csI[ky*512 + wg + 32*p];
#pragma unroll
        for (int oo = 0; oo < 4; oo++){
            u64 G = *(const u64*)&sG[(og*4 + oo)*64 + ky];
#pragma unroll
            for (int p = 0; p < 8; p++)
                acc[oo][p] = fma2(G, T[p], acc[oo][p]);
        }
    }
#pragma unroll
    for (int oo = 0; oo < 4; oo++){
        int o = og*4 + oo;
#pragma unroll
        for (int p = 0; p < 8; p++){
            int w = wg + 32*p;
            float2 uv = upk(acc[oo][p]);
            sCv[o*512 + w] = uv.x - uv.y;
            if (w) sCv[o*512 + 512 - w] = uv.x + uv.y;
        }
    }
    if (tid < 16){
        float s = 0.0f;
        for (int k = 0; k < 64; k++){
            float coef = (k == 0 ? 1.0f : 2.0f) * ((k & 1) ? -3.814697265625e-06f
                                                           :  3.814697265625e-06f);
            s += sG[tid*64 + k].x * coef;
        }
        sCv[tid*512 + 256] = s;
    }
    __syncthreads();

    u64 a0[16] = {}, a1[16] = {};
    const float* xh = x + (size_t)h*512 + 2*tid;
#pragma unroll 4
    for (int i = 0; i < 64; i++){
        u64 X0 = *(const u64*)&xh[(size_t)i*262144];
        u64 X1 = *(const u64*)&xh[(size_t)i*262144 + 256];
#pragma unroll
        for (int oo = 0; oo < 16; oo++){
            u64 W = sW[oo*64 + i];
            a0[oo] = fma2(W, X0, a0[oo]);
            a1[oo] = fma2(W, X1, a1[oo]);
        }
    }

#pragma unroll
    for (int oo = 0; oo < 16; oo++){
        int o = o0 + oo;
        float bias = b_conv[o] + b_skip[o];
        float2 c0 = *(const float2*)&sCv[oo*512 + 2*tid];
        float2 c1 = *(const float2*)&sCv[oo*512 + 256 + 2*tid];
        float2 s0 = upk(a0[oo]), s1 = upk(a1[oo]);
        float2 r0 = make_float2(gelu_t(s0.x + c0.x + bias), gelu_t(s0.y + c0.y + bias));
        float2 r1 = make_float2(gelu_t(s1.x + c1.x + bias), gelu_t(s1.y + c1.y + bias));
        size_t obase = (size_t)o*262144 + (size_t)h*512 + 2*tid;
        *(float2*)&out[obase]       = r0;
        *(float2*)&out[obase + 256] = r1;
    }
}

extern "C" void kernel_launch(void* const* d_in, const int* in_sizes, int n_in,
                              void* d_out, int out_size){
    const float* x      = (const float*)d_in[0];
    const float* w_real = (const float*)d_in[1];
    const float* w_imag = (const float*)d_in[2];
    const float* b_conv = (const float*)d_in[3];
    const float* w_skip = (const float*)d_in[4];
    const float* b_skip = (const float*)d_in[5];
    float* out = (float*)d_out;

    // capture slot (launch index 3) = k1_fwd_h
    k_tables<<<128, 256>>>();
    k_tables<<<128, 256>>>();
    k_tables<<<128, 256>>>();
    k1_fwd_h<<<dim3(8, 64), 256>>>(x);
    k2_fwd_w<<<dim3(128, 2), 256>>>();
    k3_spectral<<<dim3(16, 64), 128>>>(w_real, w_imag);
    k4_inv_h<<<dim3(8, 64), 256>>>();
    k5_inv_w<<<dim3(4, 512), 128>>>(x, b_conv, w_skip, b_skip, out);
}

// round 14
// speedup vs baseline: 1.4139x; 1.1082x over previous
#include <cuda_runtime.h>
#include <math.h>

typedef unsigned long long u64;
#define HSZ 512
#define NM  64

__device__ float  d_cF[NM*HSZ], d_sF[NM*HSZ], d_cI[NM*HSZ], d_sI[NM*HSZ];
__device__ float2 d_csI[NM*HSZ];               // interleaved (cI, sI) for K5
__device__ float2 d_t1[64*NM*HSZ];             // interleaved (tr, ti)
__device__ float2 d_xsp[2][64*NM*NM];          // K2 partial sums (w-halves)
__device__ float2 d_yf[64*NM*NM];              // interleaved (yr, yi)
__device__ float2 d_g[64*HSZ*NM];

__device__ __forceinline__ u64 pk(float lo, float hi){
    u64 r; asm("mov.b64 %0,{%1,%2};" : "=l"(r) : "f"(lo), "f"(hi)); return r; }
__device__ __forceinline__ u64 fma2(u64 a, u64 b, u64 c){
    u64 d; asm("fma.rn.f32x2 %0,%1,%2,%3;" : "=l"(d) : "l"(a), "l"(b), "l"(c)); return d; }
__device__ __forceinline__ float2 upk(u64 a){
    float2 f; asm("mov.b64 {%0,%1},%2;" : "=f"(f.x), "=f"(f.y) : "l"(a)); return f; }
__device__ __forceinline__ float gelu_t(float v){
    float u = 0.7978845608028654f * (v + 0.044715f * v * v * v), t;
    asm("tanh.approx.f32 %0,%1;" : "=f"(t) : "f"(u));
    return 0.5f * v * (1.0f + t); }

__global__ void k_tables(){
    int idx = blockIdx.x * 256 + threadIdx.x;
    int k = idx >> 9, n = idx & 511, t = (k * n) & 511;
    float s, c; sincosf((float)t * 0.012271846303085129f, &s, &c);
    d_cF[idx] = c; d_sF[idx] = s;
    float a = (k == 0 ? 1.0f : 2.0f) * (1.0f / 262144.0f);
    d_cI[idx] = a * c; d_sI[idx] = a * s;
    d_csI[idx] = make_float2(a * c, a * s);
}

// ============ K1 v4: double fold, w-tile 64 (R13) ============
__global__ void __launch_bounds__(256, 4) k1_fwd_h(const float* __restrict__ x){
    __shared__ float sAe[16][64], sAo[16][64], sBe[16][64], sBo[16][64];
    __shared__ u64 sCt[16][65], sSn[16][65];
    int tid = threadIdx.x, c = blockIdx.y, w0 = blockIdx.x * 64;
    int tw2 = (tid & 15) * 2;
    int g = tid >> 4;
    int par = g >> 3;
    int kbase = (g & 7) * 8 + par;
    const float* xc = x + (size_t)c * 262144;

    u64 aR[4][2] = {}, aI[4][2] = {};
    for (int h0 = 0; h0 < 128; h0 += 16){
        __syncthreads();
        {   int r = tid >> 4, wq = (tid & 15) * 4;
            int hf = h0 + r;
            const float* pa = &xc[(size_t)hf*512 + w0 + wq];
            const float* pb = &xc[(size_t)((512 - hf) & 511)*512 + w0 + wq];
            const float* pc = &xc[(size_t)(256 - hf)*512 + w0 + wq];
            const float* pd = &xc[(size_t)(256 + hf)*512 + w0 + wq];
            float pe = (hf == 0) ? 0.0f : 1.0f;
            float4 va = *(const float4*)pa;
            float4 vb = *(const float4*)pb;
            float4 vc = *(const float4*)pc;
            float4 vd = *(const float4*)pd;
            float4 e4, o4, be4, bo4;
#pragma unroll
            for (int e = 0; e < 4; e++){
                float fa = (&va.x)[e], fb = (&vb.x)[e];
                float fc = (&vc.x)[e] * pe, fd = (&vd.x)[e] * pe;
                float sab = fa + fb, dab = fa - fb;
                float scd = fc + fd, dcd = fc - fd;
                (&e4.x)[e]  = sab + scd;
                (&o4.x)[e]  = sab - scd;
                (&be4.x)[e] = dab - dcd;
                (&bo4.x)[e] = dab + dcd;
            }
            *(float4*)&sAe[r][wq] = e4;
            *(float4*)&sAo[r][wq] = o4;
            *(float4*)&sBe[r][wq] = be4;
            *(float4*)&sBo[r][wq] = bo4;
        }
        {   int kx = tid >> 2, hq = (tid & 3) * 4;
            float4 vc = *(const float4*)&d_cF[kx*512 + h0 + hq];
            float4 vs = *(const float4*)&d_sF[kx*512 + h0 + hq];
            sCt[hq+0][kx]=pk(vc.x,vc.x); sCt[hq+1][kx]=pk(vc.y,vc.y);
            sCt[hq+2][kx]=pk(vc.z,vc.z); sCt[hq+3][kx]=pk(vc.w,vc.w);
            sSn[hq+0][kx]=pk(-vs.x,-vs.x); sSn[hq+1][kx]=pk(-vs.y,-vs.y);
            sSn[hq+2][kx]=pk(-vs.z,-vs.z); sSn[hq+3][kx]=pk(-vs.w,-vs.w);
        }
        __syncthreads();
        const float* rowA = par ? &sAo[0][0] : &sAe[0][0];
        const float* rowB = par ? &sBo[0][0] : &sBe[0][0];
#pragma unroll 4
        for (int hh = 0; hh < 16; hh++){
            u64 A0 = *(const u64*)&rowA[hh*64 + tw2];
            u64 A1 = *(const u64*)&rowA[hh*64 + tw2 + 32];
            u64 B0 = *(const u64*)&rowB[hh*64 + tw2];
            u64 B1 = *(const u64*)&rowB[hh*64 + tw2 + 32];
#pragma unroll
            for (int j = 0; j < 4; j++){
                u64 C = sCt[hh][kbase + 2*j], S = sSn[hh][kbase + 2*j];
                aR[j][0] = fma2(C, A0, aR[j][0]);
                aR[j][1] = fma2(C, A1, aR[j][1]);
                aI[j][0] = fma2(S, B0, aI[j][0]);
                aI[j][1] = fma2(S, B1, aI[j][1]);
            }
        }
    }

    float x0v[4], x2v[4], a128[4], b128[4];
#pragma unroll
    for (int p = 0; p < 2; p++){
        float2 v0 = *(const float2*)&xc[w0 + tw2 + 32*p];
        float2 v2 = *(const float2*)&xc[(size_t)256*512 + w0 + tw2 + 32*p];
        float2 va = *(const float2*)&xc[(size_t)128*512 + w0 + tw2 + 32*p];
        float2 vb = *(const float2*)&xc[(size_t)384*512 + w0 + tw2 + 32*p];
        x0v[2*p]=v0.x; x0v[2*p+1]=v0.y;
        x2v[2*p]=v2.x; x2v[2*p+1]=v2.y;
        a128[2*p]=va.x+vb.x; a128[2*p+1]=va.y+vb.y;
        b128[2*p]=va.x-vb.x; b128[2*p+1]=va.y-vb.y;
    }
#pragma unroll
    for (int j = 0; j < 4; j++){
        int kx = kbase + 2*j;
        float js = (j & 1) ? -1.0f : 1.0f;
        size_t b = ((size_t)(c*64 + kx))*512 + w0 + tw2;
#pragma unroll
        for (int p = 0; p < 2; p++){
            float2 tr = upk(aR[j][p]), ti = upk(aI[j][p]);
            if (par == 0){
                tr.x += x2v[2*p]   - x0v[2*p]   + js * a128[2*p];
                tr.y += x2v[2*p+1] - x0v[2*p+1] + js * a128[2*p+1];
            } else {
                tr.x += -x2v[2*p]   - x0v[2*p];
                tr.y += -x2v[2*p+1] - x0v[2*p+1];
                ti.x -= js * b128[2*p];
                ti.y -= js * b128[2*p+1];
            }
            *(float4*)&d_t1[b + 32*p] = make_float4(tr.x, ti.x, tr.y, ti.y);
        }
    }
}

// ============ K2 v4: packed complex, conflict-free (R10) ============
__global__ void __launch_bounds__(256) k2_fwd_w(){
    __shared__ float2 sT[32][33];
    __shared__ u64 sC[32][65], sS[32][65];
    int tid = threadIdx.x, ck0 = blockIdx.x * 32, wbase = blockIdx.y * 256;
    int kyl = tid & 15, tck2 = (tid >> 4) * 2;
    u64 a1[2][4] = {}, a2[2][4] = {};
    for (int it = 0; it < 8; it++){
        int w0 = wbase + it * 32;
        __syncthreads();
        { int ckl = tid >> 3, wq = (tid & 7) * 4;
          const float4* tp = (const float4*)&d_t1[(size_t)(ck0+ckl)*512 + w0 + wq];
          float4 v0 = tp[0], v1 = tp[1];
          sT[wq+0][ckl] = make_float2(v0.x, v0.y);
          sT[wq+1][ckl] = make_float2(v0.z, v0.w);
          sT[wq+2][ckl] = make_float2(v1.x, v1.y);
          sT[wq+3][ckl] = make_float2(v1.z, v1.w); }
        { int ky = tid >> 2, w8 = (tid & 3) * 8;
          const float4* cp = (const float4*)&d_cF[ky*512 + w0 + w8];
          const float4* sp = (const float4*)&d_sF[ky*512 + w0 + w8];
          float4 c0 = cp[0], c1 = cp[1], s0 = sp[0], s1 = sp[1];
          sC[w8+0][ky]=pk(c0.x,c0.x); sC[w8+1][ky]=pk(c0.y,c0.y);
          sC[w8+2][ky]=pk(c0.z,c0.z); sC[w8+3][ky]=pk(c0.w,c0.w);
          sC[w8+4][ky]=pk(c1.x,c1.x); sC[w8+5][ky]=pk(c1.y,c1.y);
          sC[w8+6][ky]=pk(c1.z,c1.z); sC[w8+7][ky]=pk(c1.w,c1.w);
          sS[w8+0][ky]=pk(s0.x,s0.x); sS[w8+1][ky]=pk(s0.y,s0.y);
          sS[w8+2][ky]=pk(s0.z,s0.z); sS[w8+3][ky]=pk(s0.w,s0.w);
          sS[w8+4][ky]=pk(s1.x,s1.x); sS[w8+5][ky]=pk(s1.y,s1.y);
          sS[w8+6][ky]=pk(s1.z,s1.z); sS[w8+7][ky]=pk(s1.w,s1.w); }
        __syncthreads();
#pragma unroll 4
        for (int ww = 0; ww < 32; ww++){
            u64 T0 = *(const u64*)&sT[ww][tck2];
            u64 T1 = *(const u64*)&sT[ww][tck2+1];
#pragma unroll
            for (int q = 0; q < 4; q++){
                u64 C = sC[ww][kyl + 16*q], S = sS[ww][kyl + 16*q];
                a1[0][q] = fma2(T0, C, a1[0][q]);  a2[0][q] = fma2(T0, S, a2[0][q]);
                a1[1][q] = fma2(T1, C, a1[1][q]);  a2[1][q] = fma2(T1, S, a2[1][q]);
            }
        }
    }
#pragma unroll
    for (int j = 0; j < 2; j++){
        size_t row = (size_t)(ck0 + tck2 + j)*64;
#pragma unroll
        for (int q = 0; q < 4; q++){
            float2 v1 = upk(a1[j][q]), v2 = upk(a2[j][q]);
            d_xsp[blockIdx.y][row + kyl + 16*q] = make_float2(v1.x + v2.y, v1.y - v2.x);
        }
    }
}

// ============ K3 v4: 1024 blocks (R13) ============
__global__ void __launch_bounds__(128) k3_spectral(const float* __restrict__ wr_,
                                                   const float* __restrict__ wi_){
    __shared__ float2 sX[4096];
    int tid = threadIdx.x, kx = blockIdx.y;
    int o = blockIdx.x * 4 + (tid >> 5), ky2 = (tid & 31) * 2;
#pragma unroll
    for (int p = 0; p < 32; p++){
        int idx = tid + 128*p;
        size_t g = ((size_t)(idx >> 6))*4096 + kx*64 + (idx & 63);
        float2 a = d_xsp[0][g], b = d_xsp[1][g];
        sX[idx] = make_float2(a.x + b.x, a.y + b.y);
    }
    __syncthreads();
    float2 accR = {0,0}, accI = {0,0};
#pragma unroll 8
    for (int i = 0; i < 64; i++){
        size_t wb = ((size_t)((i*64 + o)*64 + kx))*64 + ky2;
        float2 wr = *(const float2*)&wr_[wb], wi = *(const float2*)&wi_[wb];
        float2 x0 = sX[i*64 + ky2], x1 = sX[i*64 + ky2 + 1];
        accR.x += x0.x*wr.x - x0.y*wi.x;  accI.x += x0.x*wi.x + x0.y*wr.x;
        accR.y += x1.x*wr.y - x1.y*wi.y;  accI.y += x1.x*wi.y + x1.y*wr.y;
    }
    size_t ob = (size_t)(o*64 + kx)*64 + ky2;
    *(float4*)&d_yf[ob] = make_float4(accR.x, accI.x, accR.y, accI.y);
}

// ============ K4 v2: packed complex, conflict-free (R12) ============
__global__ void __launch_bounds__(256, 2) k4_inv_h(){
    __shared__ float2 sY[32][64];
    __shared__ u64 sC[32][64], sS[32][64];
    int tid = threadIdx.x, h0 = blockIdx.x * 64, o = blockIdx.y;
    int hs = tid >> 3, kyl = tid & 7;
    u64 a1[2][8] = {}, a2[2][8] = {};
    for (int kx0 = 0; kx0 < 64; kx0 += 32){
        __syncthreads();
        {   int kxl = tid >> 3, kq = (tid & 7) * 8;
            const float4* yp = (const float4*)&d_yf[(size_t)(o*64 + kx0 + kxl)*64 + kq];
            float4 v0 = yp[0], v1 = yp[1], v2 = yp[2], v3 = yp[3];
            *(float4*)&sY[kxl][kq]   = v0;
            *(float4*)&sY[kxl][kq+2] = v1;
            *(float4*)&sY[kxl][kq+4] = v2;
            *(float4*)&sY[kxl][kq+6] = v3;
        }
        {   int kxl = tid >> 3, hq = (tid & 7) * 8;
            const float4* cp = (const float4*)&d_cF[(kx0+kxl)*512 + h0 + hq];
            const float4* sp = (const float4*)&d_sF[(kx0+kxl)*512 + h0 + hq];
            float4 c0 = cp[0], c1 = cp[1], s0 = sp[0], s1 = sp[1];
            sC[kxl][hq+0]=pk(c0.x,c0.x); sC[kxl][hq+1]=pk(c0.y,c0.y);
            sC[kxl][hq+2]=pk(c0.z,c0.z); sC[kxl][hq+3]=pk(c0.w,c0.w);
            sC[kxl][hq+4]=pk(c1.x,c1.x); sC[kxl][hq+5]=pk(c1.y,c1.y);
            sC[kxl][hq+6]=pk(c1.z,c1.z); sC[kxl][hq+7]=pk(c1.w,c1.w);
            sS[kxl][hq+0]=pk(s0.x,s0.x); sS[kxl][hq+1]=pk(s0.y,s0.y);
            sS[kxl][hq+2]=pk(s0.z,s0.z); sS[kxl][hq+3]=pk(s0.w,s0.w);
            sS[kxl][hq+4]=pk(s1.x,s1.x); sS[kxl][hq+5]=pk(s1.y,s1.y);
            sS[kxl][hq+6]=pk(s1.z,s1.z); sS[kxl][hq+7]=pk(s1.w,s1.w);
        }
        __syncthreads();
#pragma unroll 4
        for (int k = 0; k < 32; k++){
            u64 Y[8];
#pragma unroll
            for (int q = 0; q < 8; q++)
                Y[q] = *(const u64*)&sY[k][kyl + 8*q];
#pragma unroll
            for (int jh = 0; jh < 2; jh++){
                u64 C = sC[k][2*hs + jh], S = sS[k][2*hs + jh];
#pragma unroll
                for (int q = 0; q < 8; q++){
                    a1[jh][q] = fma2(Y[q], C, a1[jh][q]);
                    a2[jh][q] = fma2(Y[q], S, a2[jh][q]);
                }
            }
        }
    }
#pragma unroll
    for (int jh = 0; jh < 2; jh++){
        int h = h0 + 2*hs + jh;
#pragma unroll
        for (int q = 0; q < 8; q++){
            float2 v1 = upk(a1[jh][q]), v2 = upk(a2[jh][q]);
            d_g[((size_t)o*512 + h)*64 + kyl + 8*q] =
                make_float2(v1.x - v2.y, v1.y + v2.x);
        }
    }
}

// ============ K5 v3: quarter-wave folded conv + skip + bias + gelu ============
// Split u,v into even/odd-ky partials; one pass over w<128 yields conv at
// w, 256-w, 256+w, 512-w.  w=128/384 via small tail (table column 128).
__global__ void __launch_bounds__(128, 4) k5_inv_w(const float* __restrict__ x,
        const float* __restrict__ b_conv, const float* __restrict__ w_skip,
        const float* __restrict__ b_skip, float* __restrict__ out){
    __shared__ float2 sG[16*64];
    __shared__ u64    sW[16*64];
    __shared__ float  sCv[16*512];

    int tid = threadIdx.x, o0 = blockIdx.x * 16, h = blockIdx.y;
    int og = tid >> 5, wg = tid & 31;

#pragma unroll
    for (int q = 0; q < 8; q++){
        int id = tid + 128*q, oo = id >> 6, k = id & 63;
        sG[id] = d_g[((size_t)(o0+oo)*512 + h)*64 + k];
        float wv = w_skip[(o0+oo)*64 + k];
        sW[id] = pk(wv, wv);
    }
    __syncthreads();

    // conv: accE=(ue,ve), accO=(uo,vo) over w = wg + 32p, p<4 (w in 0..127)
    u64 accE[4][4] = {}, accO[4][4] = {};
#pragma unroll 2
    for (int kp = 0; kp < 32; kp++){
        u64 TE[4], TO[4];
#pragma unroll
        for (int p = 0; p < 4; p++){
            TE[p] = *(const u64*)&d_csI[(2*kp)*512   + wg + 32*p];
            TO[p] = *(const u64*)&d_csI[(2*kp+1)*512 + wg + 32*p];
        }
#pragma unroll
        for (int oo = 0; oo < 4; oo++){
            u64 GE = *(const u64*)&sG[(og*4 + oo)*64 + 2*kp];
            u64 GO = *(const u64*)&sG[(og*4 + oo)*64 + 2*kp + 1];
#pragma unroll
            for (int p = 0; p < 4; p++){
                accE[oo][p] = fma2(GE, TE[p], accE[oo][p]);
                accO[oo][p] = fma2(GO, TO[p], accO[oo][p]);
            }
        }
    }
#pragma unroll
    for (int oo = 0; oo < 4; oo++){
        int ob = (og*4 + oo)*512;
#pragma unroll
        for (int p = 0; p < 4; p++){
            int w = wg + 32*p;
            float2 e = upk(accE[oo][p]), od = upk(accO[oo][p]);
            float u  = e.x + od.x, v  = e.y + od.y;
            float um = e.x - od.x, vm = od.y - e.y;
            sCv[ob + w] = u - v;
            sCv[ob + 256 - w] = um - vm;
            if (w){
                sCv[ob + 512 - w] = u + v;
                sCv[ob + 256 + w] = um + vm;
            }
        }
    }
    if (tid < 16){
        float a = 0.0f, b = 0.0f;
        for (int ky = 0; ky < 64; ky++){
            float2 cs = d_csI[ky*512 + 128];
            float2 gv = sG[tid*64 + ky];
            a += gv.x * cs.x;
            b += gv.y * cs.y;
        }
        sCv[tid*512 + 128] = a - b;
        sCv[tid*512 + 384] = a + b;
    }
    __syncthreads();

    // skip: thread = 16 oo x w-pairs (2*tid, 2*tid+256)
    u64 a0[16] = {}, a1[16] = {};
    const float* xh = x + (size_t)h*512 + 2*tid;
#pragma unroll 4
    for (int i = 0; i < 64; i++){
        u64 X0 = *(const u64*)&xh[(size_t)i*262144];
        u64 X1 = *(const u64*)&xh[(size_t)i*262144 + 256];
#pragma unroll
        for (int oo = 0; oo < 16; oo++){
            u64 W = sW[oo*64 + i];
            a0[oo] = fma2(W, X0, a0[oo]);
            a1[oo] = fma2(W, X1, a1[oo]);
        }
    }

#pragma unroll
    for (int oo = 0; oo < 16; oo++){
        int o = o0 + oo;
        float bias = b_conv[o] + b_skip[o];
        float2 c0 = *(const float2*)&sCv[oo*512 + 2*tid];
        float2 c1 = *(const float2*)&sCv[oo*512 + 256 + 2*tid];
        float2 s0 = upk(a0[oo]), s1 = upk(a1[oo]);
        float2 r0 = make_float2(gelu_t(s0.x + c0.x + bias), gelu_t(s0.y + c0.y + bias));
        float2 r1 = make_float2(gelu_t(s1.x + c1.x + bias), gelu_t(s1.y + c1.y + bias));
        size_t obase = (size_t)o*262144 + (size_t)h*512 + 2*tid;
        *(float2*)&out[obase]       = r0;
        *(float2*)&out[obase + 256] = r1;
    }
}

extern "C" void kernel_launch(void* const* d_in, const int* in_sizes, int n_in,
                              void* d_out, int out_size){
    const float* x      = (const float*)d_in[0];
    const float* w_real = (const float*)d_in[1];
    const float* w_imag = (const float*)d_in[2];
    const float* b_conv = (const float*)d_in[3];
    const float* w_skip = (const float*)d_in[4];
    const float* b_skip = (const float*)d_in[5];
    float* out = (float*)d_out;

    // capture slot (launch index 3) = k2_fwd_w
    k_tables<<<128, 256>>>();
    k_tables<<<128, 256>>>();
    k1_fwd_h<<<dim3(8, 64), 256>>>(x);
    k2_fwd_w<<<dim3(128, 2), 256>>>();
    k3_spectral<<<dim3(16, 64), 128>>>(w_real, w_imag);
    k4_inv_h<<<dim3(8, 64), 256>>>();
    k5_inv_w<<<dim3(4, 512), 128>>>(x, b_conv, w_skip, b_skip, out);
}

// round 15
// speedup vs baseline: 1.6054x; 1.1354x over previous
#include <cuda_runtime.h>
#include <math.h>

typedef unsigned long long u64;
#define HSZ 512
#define NM  64

__device__ float  d_cF[NM*HSZ], d_sF[NM*HSZ], d_cI[NM*HSZ], d_sI[NM*HSZ];
__device__ float2 d_csI[NM*HSZ];               // interleaved (cI, sI) for K5
__device__ float2 d_t1[64*NM*HSZ];             // interleaved (tr, ti)
__device__ float2 d_xsp[2][64*NM*NM];          // K2 partial sums (w-halves)
__device__ float2 d_yf[64*NM*NM];              // interleaved (yr, yi)
__device__ float2 d_g[64*HSZ*NM];

__device__ __forceinline__ u64 pk(float lo, float hi){
    u64 r; asm("mov.b64 %0,{%1,%2};" : "=l"(r) : "f"(lo), "f"(hi)); return r; }
__device__ __forceinline__ u64 fma2(u64 a, u64 b, u64 c){
    u64 d; asm("fma.rn.f32x2 %0,%1,%2,%3;" : "=l"(d) : "l"(a), "l"(b), "l"(c)); return d; }
__device__ __forceinline__ float2 upk(u64 a){
    float2 f; asm("mov.b64 {%0,%1},%2;" : "=f"(f.x), "=f"(f.y) : "l"(a)); return f; }
__device__ __forceinline__ float gelu_t(float v){
    float u = 0.7978845608028654f * (v + 0.044715f * v * v * v), t;
    asm("tanh.approx.f32 %0,%1;" : "=f"(t) : "f"(u));
    return 0.5f * v * (1.0f + t); }

__global__ void k_tables(){
    int idx = blockIdx.x * 256 + threadIdx.x;
    int k = idx >> 9, n = idx & 511, t = (k * n) & 511;
    float s, c; sincosf((float)t * 0.012271846303085129f, &s, &c);
    d_cF[idx] = c; d_sF[idx] = s;
    float a = (k == 0 ? 1.0f : 2.0f) * (1.0f / 262144.0f);
    d_cI[idx] = a * c; d_sI[idx] = a * s;
    d_csI[idx] = make_float2(a * c, a * s);
}

// ============ K1 v4: double fold, w-tile 64 (R13) ============
__global__ void __launch_bounds__(256, 4) k1_fwd_h(const float* __restrict__ x){
    __shared__ float sAe[16][64], sAo[16][64], sBe[16][64], sBo[16][64];
    __shared__ u64 sCt[16][65], sSn[16][65];
    int tid = threadIdx.x, c = blockIdx.y, w0 = blockIdx.x * 64;
    int tw2 = (tid & 15) * 2;
    int g = tid >> 4;
    int par = g >> 3;
    int kbase = (g & 7) * 8 + par;
    const float* xc = x + (size_t)c * 262144;

    u64 aR[4][2] = {}, aI[4][2] = {};
    for (int h0 = 0; h0 < 128; h0 += 16){
        __syncthreads();
        {   int r = tid >> 4, wq = (tid & 15) * 4;
            int hf = h0 + r;
            const float* pa = &xc[(size_t)hf*512 + w0 + wq];
            const float* pb = &xc[(size_t)((512 - hf) & 511)*512 + w0 + wq];
            const float* pc = &xc[(size_t)(256 - hf)*512 + w0 + wq];
            const float* pd = &xc[(size_t)(256 + hf)*512 + w0 + wq];
            float pe = (hf == 0) ? 0.0f : 1.0f;
            float4 va = *(const float4*)pa;
            float4 vb = *(const float4*)pb;
            float4 vc = *(const float4*)pc;
            float4 vd = *(const float4*)pd;
            float4 e4, o4, be4, bo4;
#pragma unroll
            for (int e = 0; e < 4; e++){
                float fa = (&va.x)[e], fb = (&vb.x)[e];
                float fc = (&vc.x)[e] * pe, fd = (&vd.x)[e] * pe;
                float sab = fa + fb, dab = fa - fb;
                float scd = fc + fd, dcd = fc - fd;
                (&e4.x)[e]  = sab + scd;
                (&o4.x)[e]  = sab - scd;
                (&be4.x)[e] = dab - dcd;
                (&bo4.x)[e] = dab + dcd;
            }
            *(float4*)&sAe[r][wq] = e4;
            *(float4*)&sAo[r][wq] = o4;
            *(float4*)&sBe[r][wq] = be4;
            *(float4*)&sBo[r][wq] = bo4;
        }
        {   int kx = tid >> 2, hq = (tid & 3) * 4;
            float4 vc = *(const float4*)&d_cF[kx*512 + h0 + hq];
            float4 vs = *(const float4*)&d_sF[kx*512 + h0 + hq];
            sCt[hq+0][kx]=pk(vc.x,vc.x); sCt[hq+1][kx]=pk(vc.y,vc.y);
            sCt[hq+2][kx]=pk(vc.z,vc.z); sCt[hq+3][kx]=pk(vc.w,vc.w);
            sSn[hq+0][kx]=pk(-vs.x,-vs.x); sSn[hq+1][kx]=pk(-vs.y,-vs.y);
            sSn[hq+2][kx]=pk(-vs.z,-vs.z); sSn[hq+3][kx]=pk(-vs.w,-vs.w);
        }
        __syncthreads();
        const float* rowA = par ? &sAo[0][0] : &sAe[0][0];
        const float* rowB = par ? &sBo[0][0] : &sBe[0][0];
#pragma unroll 4
        for (int hh = 0; hh < 16; hh++){
            u64 A0 = *(const u64*)&rowA[hh*64 + tw2];
            u64 A1 = *(const u64*)&rowA[hh*64 + tw2 + 32];
            u64 B0 = *(const u64*)&rowB[hh*64 + tw2];
            u64 B1 = *(const u64*)&rowB[hh*64 + tw2 + 32];
#pragma unroll
            for (int j = 0; j < 4; j++){
                u64 C = sCt[hh][kbase + 2*j], S = sSn[hh][kbase + 2*j];
                aR[j][0] = fma2(C, A0, aR[j][0]);
                aR[j][1] = fma2(C, A1, aR[j][1]);
                aI[j][0] = fma2(S, B0, aI[j][0]);
                aI[j][1] = fma2(S, B1, aI[j][1]);
            }
        }
    }

    float x0v[4], x2v[4], a128[4], b128[4];
#pragma unroll
    for (int p = 0; p < 2; p++){
        float2 v0 = *(const float2*)&xc[w0 + tw2 + 32*p];
        float2 v2 = *(const float2*)&xc[(size_t)256*512 + w0 + tw2 + 32*p];
        float2 va = *(const float2*)&xc[(size_t)128*512 + w0 + tw2 + 32*p];
        float2 vb = *(const float2*)&xc[(size_t)384*512 + w0 + tw2 + 32*p];
        x0v[2*p]=v0.x; x0v[2*p+1]=v0.y;
        x2v[2*p]=v2.x; x2v[2*p+1]=v2.y;
        a128[2*p]=va.x+vb.x; a128[2*p+1]=va.y+vb.y;
        b128[2*p]=va.x-vb.x; b128[2*p+1]=va.y-vb.y;
    }
#pragma unroll
    for (int j = 0; j < 4; j++){
        int kx = kbase + 2*j;
        float js = (j & 1) ? -1.0f : 1.0f;
        size_t b = ((size_t)(c*64 + kx))*512 + w0 + tw2;
#pragma unroll
        for (int p = 0; p < 2; p++){
            float2 tr = upk(aR[j][p]), ti = upk(aI[j][p]);
            if (par == 0){
                tr.x += x2v[2*p]   - x0v[2*p]   + js * a128[2*p];
                tr.y += x2v[2*p+1] - x0v[2*p+1] + js * a128[2*p+1];
            } else {
                tr.x += -x2v[2*p]   - x0v[2*p];
                tr.y += -x2v[2*p+1] - x0v[2*p+1];
                ti.x -= js * b128[2*p];
                ti.y -= js * b128[2*p+1];
            }
            *(float4*)&d_t1[b + 32*p] = make_float4(tr.x, ti.x, tr.y, ti.y);
        }
    }
}

// ============ K2 v5: w-folded packed complex ============
// P = t1[w]+t1[512-w], M = t1[w]-t1[512-w]  (w = 0..255, w=0 self-paired)
// a1 += P(*)C, a2 += M(*)S ;  xsr = a1.x+a2.y, xsi = a1.y-a2.x
// corrections (block y==0): xs -= t1[0]; xs += (-1)^ky * t1[256]
__global__ void __launch_bounds__(256) k2_fwd_w(){
    __shared__ float2 sP[16][33], sM[16][33];
    __shared__ u64 sC[16][65], sS[16][65];
    int tid = threadIdx.x, ck0 = blockIdx.x * 32, wbase = blockIdx.y * 128;
    int kyl = tid & 15, tck2 = (tid >> 4) * 2;
    u64 a1[2][4] = {}, a2[2][4] = {};
    for (int it = 0; it < 8; it++){
        int w0 = wbase + it * 16;
        __syncthreads();
        {   // P/M staging: 2 consecutive w-slots per thread
            int s = tid * 2, ck = s >> 4, wl = s & 15;
            const float2* rowp = &d_t1[(size_t)(ck0+ck)*512];
#pragma unroll
            for (int e = 0; e < 2; e++){
                int w = w0 + wl + e;
                float2 f = rowp[w];
                float2 m = rowp[(512 - w) & 511];
                sP[wl+e][ck] = make_float2(f.x + m.x, f.y + m.y);
                sM[wl+e][ck] = make_float2(f.x - m.x, f.y - m.y);
            }
        }
        {   int ky = tid >> 2, wq = (tid & 3) * 4;
            float4 c4 = *(const float4*)&d_cF[ky*512 + w0 + wq];
            float4 s4 = *(const float4*)&d_sF[ky*512 + w0 + wq];
            sC[wq+0][ky]=pk(c4.x,c4.x); sC[wq+1][ky]=pk(c4.y,c4.y);
            sC[wq+2][ky]=pk(c4.z,c4.z); sC[wq+3][ky]=pk(c4.w,c4.w);
            sS[wq+0][ky]=pk(s4.x,s4.x); sS[wq+1][ky]=pk(s4.y,s4.y);
            sS[wq+2][ky]=pk(s4.z,s4.z); sS[wq+3][ky]=pk(s4.w,s4.w);
        }
        __syncthreads();
#pragma unroll 4
        for (int ww = 0; ww < 16; ww++){
            u64 P0 = *(const u64*)&sP[ww][tck2];
            u64 P1 = *(const u64*)&sP[ww][tck2+1];
            u64 M0 = *(const u64*)&sM[ww][tck2];
            u64 M1 = *(const u64*)&sM[ww][tck2+1];
#pragma unroll
            for (int q = 0; q < 4; q++){
                u64 C = sC[ww][kyl + 16*q], S = sS[ww][kyl + 16*q];
                a1[0][q] = fma2(P0, C, a1[0][q]);  a2[0][q] = fma2(M0, S, a2[0][q]);
                a1[1][q] = fma2(P1, C, a1[1][q]);  a2[1][q] = fma2(M1, S, a2[1][q]);
            }
        }
    }
#pragma unroll
    for (int j = 0; j < 2; j++){
        int row = ck0 + tck2 + j;
        float2 z0 = make_float2(0.f, 0.f), z2 = make_float2(0.f, 0.f);
        if (blockIdx.y == 0){
            z0 = d_t1[(size_t)row*512];
            z2 = d_t1[(size_t)row*512 + 256];
        }
        float sg = (kyl & 1) ? -1.0f : 1.0f;
#pragma unroll
        for (int q = 0; q < 4; q++){
            float2 v1 = upk(a1[j][q]), v2 = upk(a2[j][q]);
            float xr = v1.x + v2.y - z0.x + sg * z2.x;
            float xi = v1.y - v2.x - z0.y + sg * z2.y;
            d_xsp[blockIdx.y][(size_t)row*64 + kyl + 16*q] = make_float2(xr, xi);
        }
    }
}

// ============ K3 v4: 1024 blocks (R13) ============
__global__ void __launch_bounds__(128) k3_spectral(const float* __restrict__ wr_,
                                                   const float* __restrict__ wi_){
    __shared__ float2 sX[4096];
    int tid = threadIdx.x, kx = blockIdx.y;
    int o = blockIdx.x * 4 + (tid >> 5), ky2 = (tid & 31) * 2;
#pragma unroll
    for (int p = 0; p < 32; p++){
        int idx = tid + 128*p;
        size_t g = ((size_t)(idx >> 6))*4096 + kx*64 + (idx & 63);
        float2 a = d_xsp[0][g], b = d_xsp[1][g];
        sX[idx] = make_float2(a.x + b.x, a.y + b.y);
    }
    __syncthreads();
    float2 accR = {0,0}, accI = {0,0};
#pragma unroll 8
    for (int i = 0; i < 64; i++){
        size_t wb = ((size_t)((i*64 + o)*64 + kx))*64 + ky2;
        float2 wr = *(const float2*)&wr_[wb], wi = *(const float2*)&wi_[wb];
        float2 x0 = sX[i*64 + ky2], x1 = sX[i*64 + ky2 + 1];
        accR.x += x0.x*wr.x - x0.y*wi.x;  accI.x += x0.x*wi.x + x0.y*wr.x;
        accR.y += x1.x*wr.y - x1.y*wi.y;  accI.y += x1.x*wi.y + x1.y*wr.y;
    }
    size_t ob = (size_t)(o*64 + kx)*64 + ky2;
    *(float4*)&d_yf[ob] = make_float4(accR.x, accI.x, accR.y, accI.y);
}

// ============ K4 v3: packed complex + free mirror outputs ============
// g[h]     = (a1.x - a2.y, a1.y + a2.x)
// g[512-h] = (a1.x + a2.y, a1.y - a2.x)   (h != 0)
__global__ void __launch_bounds__(256, 2) k4_inv_h(){
    __shared__ float2 sY[32][64];
    __shared__ u64 sC[32][64], sS[32][64];
    int tid = threadIdx.x, h0 = blockIdx.x * 64, o = blockIdx.y;
    int hs = tid >> 3, kyl = tid & 7;
    u64 a1[2][8] = {}, a2[2][8] = {};
    for (int kx0 = 0; kx0 < 64; kx0 += 32){
        __syncthreads();
        {   int kxl = tid >> 3, kq = (tid & 7) * 8;
            const float4* yp = (const float4*)&d_yf[(size_t)(o*64 + kx0 + kxl)*64 + kq];
            float4 v0 = yp[0], v1 = yp[1], v2 = yp[2], v3 = yp[3];
            *(float4*)&sY[kxl][kq]   = v0;
            *(float4*)&sY[kxl][kq+2] = v1;
            *(float4*)&sY[kxl][kq+4] = v2;
            *(float4*)&sY[kxl][kq+6] = v3;
        }
        {   int kxl = tid >> 3, hq = (tid & 7) * 8;
            const float4* cp = (const float4*)&d_cF[(kx0+kxl)*512 + h0 + hq];
            const float4* sp = (const float4*)&d_sF[(kx0+kxl)*512 + h0 + hq];
            float4 c0 = cp[0], c1 = cp[1], s0 = sp[0], s1 = sp[1];
            sC[kxl][hq+0]=pk(c0.x,c0.x); sC[kxl][hq+1]=pk(c0.y,c0.y);
            sC[kxl][hq+2]=pk(c0.z,c0.z); sC[kxl][hq+3]=pk(c0.w,c0.w);
            sC[kxl][hq+4]=pk(c1.x,c1.x); sC[kxl][hq+5]=pk(c1.y,c1.y);
            sC[kxl][hq+6]=pk(c1.z,c1.z); sC[kxl][hq+7]=pk(c1.w,c1.w);
            sS[kxl][hq+0]=pk(s0.x,s0.x); sS[kxl][hq+1]=pk(s0.y,s0.y);
            sS[kxl][hq+2]=pk(s0.z,s0.z); sS[kxl][hq+3]=pk(s0.w,s0.w);
            sS[kxl][hq+4]=pk(s1.x,s1.x); sS[kxl][hq+5]=pk(s1.y,s1.y);
            sS[kxl][hq+6]=pk(s1.z,s1.z); sS[kxl][hq+7]=pk(s1.w,s1.w);
        }
        __syncthreads();
#pragma unroll 4
        for (int k = 0; k < 32; k++){
            u64 Y[8];
#pragma unroll
            for (int q = 0; q < 8; q++)
                Y[q] = *(const u64*)&sY[k][kyl + 8*q];
#pragma unroll
            for (int jh = 0; jh < 2; jh++){
                u64 C = sC[k][2*hs + jh], S = sS[k][2*hs + jh];
#pragma unroll
                for (int q = 0; q < 8; q++){
                    a1[jh][q] = fma2(Y[q], C, a1[jh][q]);
                    a2[jh][q] = fma2(Y[q], S, a2[jh][q]);
                }
            }
        }
    }
#pragma unroll
    for (int jh = 0; jh < 2; jh++){
        int h = h0 + 2*hs + jh;
        float2* gd = &d_g[((size_t)o*512 + h)*64];
        float2* gm = &d_g[((size_t)o*512 + (512 - h))*64];
#pragma unroll
        for (int q = 0; q < 8; q++){
            float2 v1 = upk(a1[jh][q]), v2 = upk(a2[jh][q]);
            gd[kyl + 8*q] = make_float2(v1.x - v2.y, v1.y + v2.x);
            if (h != 0)
                gm[kyl + 8*q] = make_float2(v1.x + v2.y, v1.y - v2.x);
        }
    }
}

// ============ K4b: g[o][256][ky] = sum_kx (-1)^kx yf[o][kx][ky] ============
__global__ void k4b_h256(){
    int o = blockIdx.x, ky = threadIdx.x;
    float2 acc = make_float2(0.f, 0.f);
    for (int kx = 0; kx < 64; kx++){
        float2 y = d_yf[(size_t)(o*64 + kx)*64 + ky];
        float sg = (kx & 1) ? -1.0f : 1.0f;
        acc.x += sg * y.x;
        acc.y += sg * y.y;
    }
    d_g[((size_t)o*512 + 256)*64 + ky] = acc;
}

// ============ K5 v3: quarter-wave folded conv + skip + bias + gelu ============
__global__ void __launch_bounds__(128, 4) k5_inv_w(const float* __restrict__ x,
        const float* __restrict__ b_conv, const float* __restrict__ w_skip,
        const float* __restrict__ b_skip, float* __restrict__ out){
    __shared__ float2 sG[16*64];
    __shared__ u64    sW[16*64];
    __shared__ float  sCv[16*512];

    int tid = threadIdx.x, o0 = blockIdx.x * 16, h = blockIdx.y;
    int og = tid >> 5, wg = tid & 31;

#pragma unroll
    for (int q = 0; q < 8; q++){
        int id = tid + 128*q, oo = id >> 6, k = id & 63;
        sG[id] = d_g[((size_t)(o0+oo)*512 + h)*64 + k];
        float wv = w_skip[(o0+oo)*64 + k];
        sW[id] = pk(wv, wv);
    }
    __syncthreads();

    u64 accE[4][4] = {}, accO[4][4] = {};
#pragma unroll 2
    for (int kp = 0; kp < 32; kp++){
        u64 TE[4], TO[4];
#pragma unroll
        for (int p = 0; p < 4; p++){
            TE[p] = *(const u64*)&d_csI[(2*kp)*512   + wg + 32*p];
            TO[p] = *(const u64*)&d_csI[(2*kp+1)*512 + wg + 32*p];
        }
#pragma unroll
        for (int oo = 0; oo < 4; oo++){
            u64 GE = *(const u64*)&sG[(og*4 + oo)*64 + 2*kp];
            u64 GO = *(const u64*)&sG[(og*4 + oo)*64 + 2*kp + 1];
#pragma unroll
            for (int p = 0; p < 4; p++){
                accE[oo][p] = fma2(GE, TE[p], accE[oo][p]);
                accO[oo][p] = fma2(GO, TO[p], accO[oo][p]);
            }
        }
    }
#pragma unroll
    for (int oo = 0; oo < 4; oo++){
        int ob = (og*4 + oo)*512;
#pragma unroll
        for (int p = 0; p < 4; p++){
            int w = wg + 32*p;
            float2 e = upk(accE[oo][p]), od = upk(accO[oo][p]);
            float u  = e.x + od.x, v  = e.y + od.y;
            float um = e.x - od.x, vm = od.y - e.y;
            sCv[ob + w] = u - v;
            sCv[ob + 256 - w] = um - vm;
            if (w){
                sCv[ob + 512 - w] = u + v;
                sCv[ob + 256 + w] = um + vm;
            }
        }
    }
    if (tid < 16){
        float a = 0.0f, b = 0.0f;
        for (int ky = 0; ky < 64; ky++){
            float2 cs = d_csI[ky*512 + 128];
            float2 gv = sG[tid*64 + ky];
            a += gv.x * cs.x;
            b += gv.y * cs.y;
        }
        sCv[tid*512 + 128] = a - b;
        sCv[tid*512 + 384] = a + b;
    }
    __syncthreads();

    u64 a0[16] = {}, a1[16] = {};
    const float* xh = x + (size_t)h*512 + 2*tid;
#pragma unroll 4
    for (int i = 0; i < 64; i++){
        u64 X0 = *(const u64*)&xh[(size_t)i*262144];
        u64 X1 = *(const u64*)&xh[(size_t)i*262144 + 256];
#pragma unroll
        for (int oo = 0; oo < 16; oo++){
            u64 W = sW[oo*64 + i];
            a0[oo] = fma2(W, X0, a0[oo]);
            a1[oo] = fma2(W, X1, a1[oo]);
        }
    }

#pragma unroll
    for (int oo = 0; oo < 16; oo++){
        int o = o0 + oo;
        float bias = b_conv[o] + b_skip[o];
        float2 c0 = *(const float2*)&sCv[oo*512 + 2*tid];
        float2 c1 = *(const float2*)&sCv[oo*512 + 256 + 2*tid];
        float2 s0 = upk(a0[oo]), s1 = upk(a1[oo]);
        float2 r0 = make_float2(gelu_t(s0.x + c0.x + bias), gelu_t(s0.y + c0.y + bias));
        float2 r1 = make_float2(gelu_t(s1.x + c1.x + bias), gelu_t(s1.y + c1.y + bias));
        size_t obase = (size_t)o*262144 + (size_t)h*512 + 2*tid;
        *(float2*)&out[obase]       = r0;
        *(float2*)&out[obase + 256] = r1;
    }
}

extern "C" void kernel_launch(void* const* d_in, const int* in_sizes, int n_in,
                              void* d_out, int out_size){
    const float* x      = (const float*)d_in[0];
    const float* w_real = (const float*)d_in[1];
    const float* w_imag = (const float*)d_in[2];
    const float* b_conv = (const float*)d_in[3];
    const float* w_skip = (const float*)d_in[4];
    const float* b_skip = (const float*)d_in[5];
    float* out = (float*)d_out;

    // capture slot (launch index 3) = k2_fwd_w
    k_tables<<<128, 256>>>();
    k_tables<<<128, 256>>>();
    k1_fwd_h<<<dim3(8, 64), 256>>>(x);
    k2_fwd_w<<<dim3(128, 2), 256>>>();
    k3_spectral<<<dim3(16, 64), 128>>>(w_real, w_imag);
    k4_inv_h<<<dim3(4, 64), 256>>>();
    k4b_h256<<<64, 64>>>();
    k5_inv_w<<<dim3(4, 512), 128>>>(x, b_conv, w_skip, b_skip, out);
}